// round 9
// baseline (speedup 1.0000x reference)
#include <cuda_runtime.h>
#include <cuda_bf16.h>
#include <cstdint>

#define NNODES 50000
#define NEDGES 800000
#define FN 32
#define FE 16
#define HID 128
#define DEPTH 4
#define NGRAPHS 128

// ---------------- scratch (device globals: allocation-free) ----------------
__device__ float g_h[NNODES * HID];
__device__ float g_h0[NNODES * HID];
__device__ float g_zin[NNODES * HID];
__device__ int   g_cnt[NNODES];
__device__ int   g_cnt2[NNODES];
__device__ int   g_rowptr[NNODES + 1];
__device__ int   g_srcPerm[NEDGES];
__device__ __align__(16) float g_eattr[NEDGES * FE];
__device__ float g_pooled[NGRAPHS * HID];
__device__ int   g_ei[2 * NEDGES];
__device__ int   g_bat[NNODES];
__device__ int   g_is64;

__device__ __forceinline__ void split_bf(float x, unsigned short& hi, unsigned short& lo) {
    __nv_bfloat16 h = __float2bfloat16(x);
    float r = x - __bfloat162float(h);
    __nv_bfloat16 l = __float2bfloat16(r);
    hi = __bfloat16_as_ushort(h);
    lo = __bfloat16_as_ushort(l);
}

__device__ __forceinline__ void mma16816(float* d, uint32_t a0, uint32_t a1, uint32_t a2, uint32_t a3,
                                         uint32_t b0, uint32_t b1) {
    asm volatile(
        "mma.sync.aligned.m16n8k16.row.col.f32.bf16.bf16.f32 "
        "{%0,%1,%2,%3}, {%4,%5,%6,%7}, {%8,%9}, {%0,%1,%2,%3};"
        : "+f"(d[0]), "+f"(d[1]), "+f"(d[2]), "+f"(d[3])
        : "r"(a0), "r"(a1), "r"(a2), "r"(a3), "r"(b0), "r"(b1));
}

// ---------------- dtype detect + merged prologue ----------------
__global__ void detect_kernel(const int* __restrict__ ei_words) {
    int is64 = 1;
    for (int i = 0; i < 256; i++)
        if (ei_words[2 * i + 1] != 0) { is64 = 0; break; }
    g_is64 = is64;
}
__global__ void prologue_kernel(const void* __restrict__ ei, const void* __restrict__ bat) {
    int i = blockIdx.x * blockDim.x + threadIdx.x;
    int is64 = g_is64;
    if (i < 2 * NEDGES)
        g_ei[i] = is64 ? (int)((const long long*)ei)[i] : ((const int*)ei)[i];
    if (i < NNODES) {
        g_bat[i] = is64 ? (int)((const long long*)bat)[i] : ((const int*)bat)[i];
        g_cnt[i] = 0;
        g_cnt2[i] = 0;
    }
    if (i < NGRAPHS * HID) g_pooled[i] = 0.f;
}

// ---------------- CSR build ----------------
__global__ void hist_kernel() {
    int e = blockIdx.x * blockDim.x + threadIdx.x;
    if (e < NEDGES) atomicAdd(&g_cnt[g_ei[NEDGES + e]], 1);
}
__global__ void scan_kernel() {
    __shared__ int warpsum[32];
    int tid = threadIdx.x, lane = tid & 31, wid = tid >> 5;
    int carry = 0;
    for (int base = 0; base < NNODES; base += 1024) {
        int i = base + tid;
        int v = (i < NNODES) ? g_cnt[i] : 0;
        int s = v;
        #pragma unroll
        for (int off = 1; off < 32; off <<= 1) {
            int t = __shfl_up_sync(0xffffffffu, s, off);
            if (lane >= off) s += t;
        }
        if (lane == 31) warpsum[wid] = s;
        __syncthreads();
        if (wid == 0) {
            int ws = warpsum[lane];
            #pragma unroll
            for (int off = 1; off < 32; off <<= 1) {
                int t = __shfl_up_sync(0xffffffffu, ws, off);
                if (lane >= off) ws += t;
            }
            warpsum[lane] = ws;
        }
        __syncthreads();
        int woff = (wid > 0) ? warpsum[wid - 1] : 0;
        if (i < NNODES) g_rowptr[i] = carry + s + woff - v;
        int total = warpsum[31];
        __syncthreads();
        carry += total;
    }
    if (tid == 0) g_rowptr[NNODES] = carry;
}
__global__ void scatter_kernel(const float* __restrict__ ea) {
    int e = blockIdx.x * blockDim.x + threadIdx.x;
    if (e >= NEDGES) return;
    int d = g_ei[NEDGES + e];
    int s = g_ei[e];
    int pos = g_rowptr[d] + atomicAdd(&g_cnt2[d], 1);
    g_srcPerm[pos] = s;
    float4* dst = (float4*)&g_eattr[(size_t)pos * FE];
    const float4* src = (const float4*)&ea[(size_t)e * FE];
    dst[0] = src[0]; dst[1] = src[1]; dst[2] = src[2]; dst[3] = src[3];
}

// ---------------- init GEMM: h = relu(x @ init_w + init_b), h0 = h ----------------
__global__ __launch_bounds__(256) void init_gemm_kernel(const float* __restrict__ X,
                                                        const float* __restrict__ W,
                                                        const float* __restrict__ B) {
    __shared__ float As[128][33];
    __shared__ float Ws[32][128];
    int tid = threadIdx.x;
    int row0 = blockIdx.x * 128;
    int tx = tid & 15, ty = tid >> 4;
    {
        int lr = tid >> 1, lc = (tid & 1) * 16;
        float4 v0, v1, v2, v3;
        if (row0 + lr < NNODES) {
            const float4* p = (const float4*)&X[(size_t)(row0 + lr) * FN + lc];
            v0 = p[0]; v1 = p[1]; v2 = p[2]; v3 = p[3];
        } else { v0 = make_float4(0.f, 0.f, 0.f, 0.f); v1 = v0; v2 = v0; v3 = v0; }
        As[lr][lc + 0] = v0.x; As[lr][lc + 1] = v0.y; As[lr][lc + 2] = v0.z; As[lr][lc + 3] = v0.w;
        As[lr][lc + 4] = v1.x; As[lr][lc + 5] = v1.y; As[lr][lc + 6] = v1.z; As[lr][lc + 7] = v1.w;
        As[lr][lc + 8] = v2.x; As[lr][lc + 9] = v2.y; As[lr][lc + 10] = v2.z; As[lr][lc + 11] = v2.w;
        As[lr][lc + 12] = v3.x; As[lr][lc + 13] = v3.y; As[lr][lc + 14] = v3.z; As[lr][lc + 15] = v3.w;
    }
    {
        int wk = tid >> 3, wc = (tid & 7) * 16;
        const float4* p = (const float4*)&W[(size_t)wk * HID + wc];
        float4 v0 = p[0], v1 = p[1], v2 = p[2], v3 = p[3];
        Ws[wk][wc + 0] = v0.x; Ws[wk][wc + 1] = v0.y; Ws[wk][wc + 2] = v0.z; Ws[wk][wc + 3] = v0.w;
        Ws[wk][wc + 4] = v1.x; Ws[wk][wc + 5] = v1.y; Ws[wk][wc + 6] = v1.z; Ws[wk][wc + 7] = v1.w;
        Ws[wk][wc + 8] = v2.x; Ws[wk][wc + 9] = v2.y; Ws[wk][wc + 10] = v2.z; Ws[wk][wc + 11] = v2.w;
        Ws[wk][wc + 12] = v3.x; Ws[wk][wc + 13] = v3.y; Ws[wk][wc + 14] = v3.z; Ws[wk][wc + 15] = v3.w;
    }
    __syncthreads();
    float acc[8][8];
    #pragma unroll
    for (int i = 0; i < 8; i++)
        #pragma unroll
        for (int j = 0; j < 8; j++) acc[i][j] = 0.f;
    #pragma unroll
    for (int kk = 0; kk < 32; kk++) {
        float a[8];
        #pragma unroll
        for (int i = 0; i < 8; i++) a[i] = As[ty * 8 + i][kk];
        float4 b0 = *(const float4*)&Ws[kk][tx * 8];
        float4 b1 = *(const float4*)&Ws[kk][tx * 8 + 4];
        float b[8] = {b0.x, b0.y, b0.z, b0.w, b1.x, b1.y, b1.z, b1.w};
        #pragma unroll
        for (int i = 0; i < 8; i++)
            #pragma unroll
            for (int j = 0; j < 8; j++) acc[i][j] += a[i] * b[j];
    }
    #pragma unroll
    for (int i = 0; i < 8; i++) {
        int r = row0 + ty * 8 + i;
        if (r < NNODES) {
            #pragma unroll
            for (int j = 0; j < 8; j++) {
                int c = tx * 8 + j;
                float v = acc[i][j] + B[c];
                v = v > 0.f ? v : 0.f;
                g_h[(size_t)r * HID + c] = v;
                g_h0[(size_t)r * HID + c] = v;
            }
        }
    }
}

// ========== fused edge-GEMM + aggregation: zin = h + sum relu(h[src] + eattr@W + b) ==========
// Block owns 64 nodes -> contiguous CSR edge range. 128-edge windows: stage eattr,
// mma.sync (split bf16) -> E in SMEM, aggregate immediately. E never hits DRAM.
#define EG_LDA 24
#define LDE 136
#define FA_NPB 64
#define FAS_AHI 0
#define FAS_ALO (FAS_AHI + 128 * EG_LDA * 2)
#define FAS_WHI (FAS_ALO + 128 * EG_LDA * 2)
#define FAS_WLO (FAS_WHI + 128 * EG_LDA * 2)
#define FAS_E   (FAS_WLO + 128 * EG_LDA * 2)
#define FAS_B   (FAS_E + 128 * LDE * 2)
#define FAS_TOTAL (FAS_B + 512)

__global__ __launch_bounds__(256) void fused_edge_aggr_kernel(const float* __restrict__ Wd,
                                                              const float* __restrict__ Bd) {
    extern __shared__ __align__(16) char smem[];
    unsigned short* sAhi = (unsigned short*)(smem + FAS_AHI);
    unsigned short* sAlo = (unsigned short*)(smem + FAS_ALO);
    unsigned short* sWhi = (unsigned short*)(smem + FAS_WHI);
    unsigned short* sWlo = (unsigned short*)(smem + FAS_WLO);
    unsigned short* sE   = (unsigned short*)(smem + FAS_E);
    float* sB = (float*)(smem + FAS_B);

    int tid = threadIdx.x, wid = tid >> 5, lane = tid & 31;
    int g = lane >> 2, t4 = lane & 3;
    int m0 = wid * 16;
    int c4 = lane * 4;

    int n0 = blockIdx.x * FA_NPB;
    int nend = min(n0 + FA_NPB, NNODES);

    // stage W transposed (hi/lo) + bias
    #pragma unroll
    for (int i = 0; i < 8; i++) {
        int idx = tid + 256 * i;           // 16*128 = 2048
        int k = idx >> 7, n = idx & 127;
        float v = Wd[idx];
        unsigned short h, l;
        split_bf(v, h, l);
        sWhi[n * EG_LDA + k] = h;
        sWlo[n * EG_LDA + k] = l;
    }
    if (tid < 128) sB[tid] = Bd[tid];

    // per-warp node range (8 nodes per warp)
    int nw0 = n0 + wid * 8;
    int rp = 0;
    if (lane < 9) rp = g_rowptr[min(nw0 + lane, nend)];
    int r0a[8], r1a[8];
    #pragma unroll
    for (int i = 0; i < 8; i++) {
        r0a[i] = __shfl_sync(0xffffffffu, rp, i);
        r1a[i] = __shfl_sync(0xffffffffu, rp, i + 1);
    }

    // init accumulators with self h
    float4 acc[8];
    #pragma unroll
    for (int i = 0; i < 8; i++) {
        int n = nw0 + i;
        acc[i] = (n < nend) ? *(const float4*)&g_h[(size_t)n * HID + c4]
                            : make_float4(0.f, 0.f, 0.f, 0.f);
    }

    int e_start = g_rowptr[n0];
    int e_end = g_rowptr[nend];

    for (int w0 = e_start; w0 < e_end; w0 += 128) {
        int cnt = min(128, e_end - w0);
        __syncthreads();   // previous window fully consumed
        // stage eattr rows [0, cnt)
        #pragma unroll
        for (int i = 0; i < 8; i++) {
            int idx = tid + 256 * i;
            if (idx < cnt * 16) {
                int row = idx >> 4, k = idx & 15;
                float v = g_eattr[(size_t)(w0 + row) * FE + k];
                unsigned short h, l;
                split_bf(v, h, l);
                sAhi[row * EG_LDA + k] = h;
                sAlo[row * EG_LDA + k] = l;
            }
        }
        __syncthreads();
        // mma: warp computes rows [m0, m0+16) of E window
        {
            float d[16][4];
            #pragma unroll
            for (int j = 0; j < 16; j++)
                #pragma unroll
                for (int q = 0; q < 4; q++) d[j][q] = 0.f;
            uint32_t ah0 = *(uint32_t*)&sAhi[(m0 + g) * EG_LDA + 2 * t4];
            uint32_t ah1 = *(uint32_t*)&sAhi[(m0 + g + 8) * EG_LDA + 2 * t4];
            uint32_t ah2 = *(uint32_t*)&sAhi[(m0 + g) * EG_LDA + 2 * t4 + 8];
            uint32_t ah3 = *(uint32_t*)&sAhi[(m0 + g + 8) * EG_LDA + 2 * t4 + 8];
            uint32_t al0 = *(uint32_t*)&sAlo[(m0 + g) * EG_LDA + 2 * t4];
            uint32_t al1 = *(uint32_t*)&sAlo[(m0 + g + 8) * EG_LDA + 2 * t4];
            uint32_t al2 = *(uint32_t*)&sAlo[(m0 + g) * EG_LDA + 2 * t4 + 8];
            uint32_t al3 = *(uint32_t*)&sAlo[(m0 + g + 8) * EG_LDA + 2 * t4 + 8];
            #pragma unroll
            for (int j = 0; j < 16; j++) {
                int nrow = j * 8 + g;
                uint32_t bh0 = *(uint32_t*)&sWhi[nrow * EG_LDA + 2 * t4];
                uint32_t bh1 = *(uint32_t*)&sWhi[nrow * EG_LDA + 2 * t4 + 8];
                uint32_t bl0 = *(uint32_t*)&sWlo[nrow * EG_LDA + 2 * t4];
                uint32_t bl1 = *(uint32_t*)&sWlo[nrow * EG_LDA + 2 * t4 + 8];
                mma16816(d[j], ah0, ah1, ah2, ah3, bh0, bh1);
                mma16816(d[j], ah0, ah1, ah2, ah3, bl0, bl1);
                mma16816(d[j], al0, al1, al2, al3, bh0, bh1);
            }
            #pragma unroll
            for (int j = 0; j < 16; j++) {
                int c = j * 8 + 2 * t4;
                float b0v = sB[c], b1v = sB[c + 1];
                unsigned short u00 = __bfloat16_as_ushort(__float2bfloat16(d[j][0] + b0v));
                unsigned short u01 = __bfloat16_as_ushort(__float2bfloat16(d[j][1] + b1v));
                unsigned short u10 = __bfloat16_as_ushort(__float2bfloat16(d[j][2] + b0v));
                unsigned short u11 = __bfloat16_as_ushort(__float2bfloat16(d[j][3] + b1v));
                *(uint32_t*)&sE[(m0 + g) * LDE + c]     = (uint32_t)u00 | ((uint32_t)u01 << 16);
                *(uint32_t*)&sE[(m0 + g + 8) * LDE + c] = (uint32_t)u10 | ((uint32_t)u11 << 16);
            }
        }
        __syncthreads();
        // aggregate this window
        int wend = w0 + cnt;
        #pragma unroll
        for (int i = 0; i < 8; i++) {
            int lo = max(r0a[i], w0);
            int hi = min(r1a[i], wend);
            for (int e = lo; e < hi; e++) {
                int s = g_srcPerm[e];
                float4 hv = *(const float4*)&g_h[(size_t)s * HID + c4];
                uint2 ev = *(const uint2*)&sE[(size_t)(e - w0) * LDE + c4];
                float e0 = __bfloat162float(__ushort_as_bfloat16((unsigned short)(ev.x & 0xFFFF)));
                float e1 = __bfloat162float(__ushort_as_bfloat16((unsigned short)(ev.x >> 16)));
                float e2 = __bfloat162float(__ushort_as_bfloat16((unsigned short)(ev.y & 0xFFFF)));
                float e3 = __bfloat162float(__ushort_as_bfloat16((unsigned short)(ev.y >> 16)));
                acc[i].x += fmaxf(hv.x + e0, 0.f);
                acc[i].y += fmaxf(hv.y + e1, 0.f);
                acc[i].z += fmaxf(hv.z + e2, 0.f);
                acc[i].w += fmaxf(hv.w + e3, 0.f);
            }
        }
    }

    #pragma unroll
    for (int i = 0; i < 8; i++) {
        int n = nw0 + i;
        if (n < nend) *(float4*)&g_zin[(size_t)n * HID + c4] = acc[i];
    }
}

// ================= fused node-MLP via mma.sync (bf16 split hi/lo) =================
#define LDH 136
#define SMF_B1 0
#define SMF_B2 512
#define SMF_AHI 1024
#define SMF_ALO (SMF_AHI + 128 * LDH * 2)
#define SMF_WHI (SMF_ALO + 128 * LDH * 2)
#define SMF_WLO (SMF_WHI + 128 * LDH * 2)
#define SMF_TOTAL (SMF_WLO + 128 * LDH * 2)

__global__ __launch_bounds__(256) void mlp_fused_kernel(
    const float* __restrict__ A, const float* __restrict__ W1, const float* __restrict__ B1,
    const float* __restrict__ W2, const float* __restrict__ B2,
    const float* __restrict__ H0, float* __restrict__ OUT)
{
    extern __shared__ __align__(16) char smem[];
    unsigned short* sAhi = (unsigned short*)(smem + SMF_AHI);
    unsigned short* sAlo = (unsigned short*)(smem + SMF_ALO);
    unsigned short* sWhi = (unsigned short*)(smem + SMF_WHI);
    unsigned short* sWlo = (unsigned short*)(smem + SMF_WLO);
    float* sB1 = (float*)(smem + SMF_B1);
    float* sB2 = (float*)(smem + SMF_B2);

    int tid = threadIdx.x, wid = tid >> 5, lane = tid & 31;
    int g = lane >> 2, t4 = lane & 3;
    int row0 = blockIdx.x * 128;
    int m0 = wid * 16;

    if (tid < 128) { sB1[tid] = B1[tid]; sB2[tid] = B2[tid]; }

    #pragma unroll
    for (int i = 0; i < 32; i++) {
        int idx2 = tid + 256 * i;
        int row = idx2 >> 6;
        int col = (idx2 & 63) * 2;
        int gr = row0 + row;
        float2 v = (gr < NNODES) ? *(const float2*)&A[(size_t)gr * HID + col]
                                 : make_float2(0.f, 0.f);
        unsigned short hx, lx, hy, ly;
        split_bf(v.x, hx, lx); split_bf(v.y, hy, ly);
        *(uint32_t*)&sAhi[row * LDH + col] = (uint32_t)hx | ((uint32_t)hy << 16);
        *(uint32_t*)&sAlo[row * LDH + col] = (uint32_t)lx | ((uint32_t)ly << 16);
    }
    #pragma unroll
    for (int i = 0; i < 64; i++) {
        int idx = tid + 256 * i;
        int k = idx >> 7;
        int n = idx & 127;
        float w = W1[idx];
        unsigned short h, l;
        split_bf(w, h, l);
        sWhi[n * LDH + k] = h;
        sWlo[n * LDH + k] = l;
    }
    __syncthreads();

    float d[16][4];
    #pragma unroll
    for (int j = 0; j < 16; j++)
        #pragma unroll
        for (int q = 0; q < 4; q++) d[j][q] = 0.f;

    #pragma unroll
    for (int ks = 0; ks < 8; ks++) {
        int k0 = ks * 16;
        uint32_t ah0 = *(uint32_t*)&sAhi[(m0 + g) * LDH + k0 + 2 * t4];
        uint32_t ah1 = *(uint32_t*)&sAhi[(m0 + g + 8) * LDH + k0 + 2 * t4];
        uint32_t ah2 = *(uint32_t*)&sAhi[(m0 + g) * LDH + k0 + 2 * t4 + 8];
        uint32_t ah3 = *(uint32_t*)&sAhi[(m0 + g + 8) * LDH + k0 + 2 * t4 + 8];
        uint32_t al0 = *(uint32_t*)&sAlo[(m0 + g) * LDH + k0 + 2 * t4];
        uint32_t al1 = *(uint32_t*)&sAlo[(m0 + g + 8) * LDH + k0 + 2 * t4];
        uint32_t al2 = *(uint32_t*)&sAlo[(m0 + g) * LDH + k0 + 2 * t4 + 8];
        uint32_t al3 = *(uint32_t*)&sAlo[(m0 + g + 8) * LDH + k0 + 2 * t4 + 8];
        #pragma unroll
        for (int j = 0; j < 16; j++) {
            int nrow = j * 8 + g;
            uint32_t bh0 = *(uint32_t*)&sWhi[nrow * LDH + k0 + 2 * t4];
            uint32_t bh1 = *(uint32_t*)&sWhi[nrow * LDH + k0 + 2 * t4 + 8];
            uint32_t bl0 = *(uint32_t*)&sWlo[nrow * LDH + k0 + 2 * t4];
            uint32_t bl1 = *(uint32_t*)&sWlo[nrow * LDH + k0 + 2 * t4 + 8];
            mma16816(d[j], ah0, ah1, ah2, ah3, bh0, bh1);
            mma16816(d[j], ah0, ah1, ah2, ah3, bl0, bl1);
            mma16816(d[j], al0, al1, al2, al3, bh0, bh1);
        }
    }

    #pragma unroll
    for (int j = 0; j < 16; j++) {
        int c = j * 8 + 2 * t4;
        float b0v = sB1[c], b1v = sB1[c + 1];
        float v00 = d[j][0] + b0v, v01 = d[j][1] + b1v;
        float v10 = d[j][2] + b0v, v11 = d[j][3] + b1v;
        v00 = v00 > 0.f ? v00 : 0.f; v01 = v01 > 0.f ? v01 : 0.f;
        v10 = v10 > 0.f ? v10 : 0.f; v11 = v11 > 0.f ? v11 : 0.f;
        unsigned short h00, l00, h01, l01, h10, l10, h11, l11;
        split_bf(v00, h00, l00); split_bf(v01, h01, l01);
        split_bf(v10, h10, l10); split_bf(v11, h11, l11);
        *(uint32_t*)&sAhi[(m0 + g) * LDH + c]     = (uint32_t)h00 | ((uint32_t)h01 << 16);
        *(uint32_t*)&sAlo[(m0 + g) * LDH + c]     = (uint32_t)l00 | ((uint32_t)l01 << 16);
        *(uint32_t*)&sAhi[(m0 + g + 8) * LDH + c] = (uint32_t)h10 | ((uint32_t)h11 << 16);
        *(uint32_t*)&sAlo[(m0 + g + 8) * LDH + c] = (uint32_t)l10 | ((uint32_t)l11 << 16);
    }
    __syncthreads();
    #pragma unroll
    for (int i = 0; i < 64; i++) {
        int idx = tid + 256 * i;
        int k = idx >> 7;
        int n = idx & 127;
        float w = W2[idx];
        unsigned short h, l;
        split_bf(w, h, l);
        sWhi[n * LDH + k] = h;
        sWlo[n * LDH + k] = l;
    }
    __syncthreads();

    #pragma unroll
    for (int j = 0; j < 16; j++)
        #pragma unroll
        for (int q = 0; q < 4; q++) d[j][q] = 0.f;

    #pragma unroll
    for (int ks = 0; ks < 8; ks++) {
        int k0 = ks * 16;
        uint32_t ah0 = *(uint32_t*)&sAhi[(m0 + g) * LDH + k0 + 2 * t4];
        uint32_t ah1 = *(uint32_t*)&sAhi[(m0 + g + 8) * LDH + k0 + 2 * t4];
        uint32_t ah2 = *(uint32_t*)&sAhi[(m0 + g) * LDH + k0 + 2 * t4 + 8];
        uint32_t ah3 = *(uint32_t*)&sAhi[(m0 + g + 8) * LDH + k0 + 2 * t4 + 8];
        uint32_t al0 = *(uint32_t*)&sAlo[(m0 + g) * LDH + k0 + 2 * t4];
        uint32_t al1 = *(uint32_t*)&sAlo[(m0 + g + 8) * LDH + k0 + 2 * t4];
        uint32_t al2 = *(uint32_t*)&sAlo[(m0 + g) * LDH + k0 + 2 * t4 + 8];
        uint32_t al3 = *(uint32_t*)&sAlo[(m0 + g + 8) * LDH + k0 + 2 * t4 + 8];
        #pragma unroll
        for (int j = 0; j < 16; j++) {
            int nrow = j * 8 + g;
            uint32_t bh0 = *(uint32_t*)&sWhi[nrow * LDH + k0 + 2 * t4];
            uint32_t bh1 = *(uint32_t*)&sWhi[nrow * LDH + k0 + 2 * t4 + 8];
            uint32_t bl0 = *(uint32_t*)&sWlo[nrow * LDH + k0 + 2 * t4];
            uint32_t bl1 = *(uint32_t*)&sWlo[nrow * LDH + k0 + 2 * t4 + 8];
            mma16816(d[j], ah0, ah1, ah2, ah3, bh0, bh1);
            mma16816(d[j], ah0, ah1, ah2, ah3, bl0, bl1);
            mma16816(d[j], al0, al1, al2, al3, bh0, bh1);
        }
    }

    {
        int gr0 = row0 + m0 + g;
        int gr1 = gr0 + 8;
        #pragma unroll
        for (int j = 0; j < 16; j++) {
            int c = j * 8 + 2 * t4;
            float b0v = sB2[c], b1v = sB2[c + 1];
            if (gr0 < NNODES) {
                float2 h0v = *(const float2*)&H0[(size_t)gr0 * HID + c];
                float2 o;
                o.x = d[j][0] + b0v + h0v.x;
                o.y = d[j][1] + b1v + h0v.y;
                o.x = o.x > 0.f ? o.x : 0.f;
                o.y = o.y > 0.f ? o.y : 0.f;
                *(float2*)&OUT[(size_t)gr0 * HID + c] = o;
            }
            if (gr1 < NNODES) {
                float2 h0v = *(const float2*)&H0[(size_t)gr1 * HID + c];
                float2 o;
                o.x = d[j][2] + b0v + h0v.x;
                o.y = d[j][3] + b1v + h0v.y;
                o.x = o.x > 0.f ? o.x : 0.f;
                o.y = o.y > 0.f ? o.y : 0.f;
                *(float2*)&OUT[(size_t)gr1 * HID + c] = o;
            }
        }
    }
}

// ---------------- pooling (batch is sorted) ----------------
__global__ void pool_kernel() {
    const int CH = 256;
    int start = blockIdx.x * CH;
    if (start >= NNODES) return;
    int end = min(start + CH, NNODES);
    int tid = threadIdx.x;
    int gcur = g_bat[start];
    float acc = 0.f;
    for (int n = start; n < end; n++) {
        int b = g_bat[n];
        if (b != gcur) {
            atomicAdd(&g_pooled[gcur * HID + tid], acc);
            acc = 0.f;
            gcur = b;
        }
        acc += g_h[(size_t)n * HID + tid];
    }
    atomicAdd(&g_pooled[gcur * HID + tid], acc);
}

__global__ void final_kernel(const float* __restrict__ fw, const float* __restrict__ fb,
                             float* __restrict__ out) {
    int g = threadIdx.x;
    float s = fb[0];
    #pragma unroll 8
    for (int c = 0; c < HID; c++) s += g_pooled[g * HID + c] * fw[c];
    out[g] = s;
}

// ---------------- launch ----------------
extern "C" void kernel_launch(void* const* d_in, const int* in_sizes, int n_in,
                              void* d_out, int out_size) {
    const float* x       = (const float*)d_in[0];
    const void*  ei      = d_in[1];
    const float* eattr   = (const float*)d_in[2];
    const void*  bat     = d_in[3];
    const float* init_w  = (const float*)d_in[4];
    const float* init_b  = (const float*)d_in[5];
    const float* edge_w  = (const float*)d_in[6];
    const float* edge_b  = (const float*)d_in[7];
    const float* mlp_w1  = (const float*)d_in[8];
    const float* mlp_b1  = (const float*)d_in[9];
    const float* mlp_w2  = (const float*)d_in[10];
    const float* mlp_b2  = (const float*)d_in[11];
    const float* ffn_w   = (const float*)d_in[12];
    const float* ffn_b   = (const float*)d_in[13];
    float* out = (float*)d_out;

    float *p_h = 0, *p_h0 = 0, *p_zin = 0;
    cudaGetSymbolAddress((void**)&p_h,   g_h);
    cudaGetSymbolAddress((void**)&p_h0,  g_h0);
    cudaGetSymbolAddress((void**)&p_zin, g_zin);

    cudaFuncSetAttribute(mlp_fused_kernel, cudaFuncAttributeMaxDynamicSharedMemorySize, SMF_TOTAL);
    cudaFuncSetAttribute(fused_edge_aggr_kernel, cudaFuncAttributeMaxDynamicSharedMemorySize, FAS_TOTAL);

    const int EBLK = (NEDGES + 255) / 256;
    const int GBLK = (NNODES + 127) / 128;
    const int PBLK = (2 * NEDGES + 255) / 256;
    const int ABLK = (NNODES + FA_NPB - 1) / FA_NPB;

    detect_kernel<<<1, 1>>>((const int*)ei);
    prologue_kernel<<<PBLK, 256>>>(ei, bat);
    hist_kernel<<<EBLK, 256>>>();
    scan_kernel<<<1, 1024>>>();
    scatter_kernel<<<EBLK, 256>>>(eattr);

    init_gemm_kernel<<<GBLK, 256>>>(x, init_w, init_b);

    for (int d = 0; d < DEPTH; d++) {
        fused_edge_aggr_kernel<<<ABLK, 256, FAS_TOTAL>>>(edge_w + (size_t)d * FE * HID,
                                                         edge_b + (size_t)d * HID);
        mlp_fused_kernel<<<GBLK, 256, SMF_TOTAL>>>(
            p_zin, mlp_w1 + (size_t)d * HID * HID, mlp_b1 + (size_t)d * HID,
            mlp_w2 + (size_t)d * HID * HID, mlp_b2 + (size_t)d * HID, p_h0, p_h);
    }

    pool_kernel<<<(NNODES + 255) / 256, 128>>>();
    final_kernel<<<1, 128>>>(ffn_w, ffn_b, out);
}

// round 10
// speedup vs baseline: 1.8969x; 1.8969x over previous
#include <cuda_runtime.h>
#include <cuda_bf16.h>
#include <cstdint>

#define NNODES 50000
#define NEDGES 800000
#define FN 32
#define FE 16
#define HID 128
#define DEPTH 4
#define NGRAPHS 128
#define SCAN_NB 49   // ceil(50000/1024)

// ---------------- scratch (device globals: allocation-free) ----------------
__device__ float g_h[NNODES * HID];
__device__ float g_h0[NNODES * HID];
__device__ float g_zin[NNODES * HID];
__device__ int   g_cnt[NNODES];
__device__ int   g_cnt2[NNODES];
__device__ int   g_rowptr[NNODES + 1];
__device__ int   g_part[SCAN_NB];
__device__ int   g_partoff[SCAN_NB + 1];
__device__ int   g_srcPerm[NEDGES];
__device__ __align__(16) float g_eattr[NEDGES * FE];
__device__ __align__(16) unsigned short g_E[(size_t)NEDGES * HID];
__device__ float g_pooled[NGRAPHS * HID];
__device__ int   g_ei[2 * NEDGES];
__device__ int   g_bat[NNODES];
__device__ int   g_is64;

__device__ __forceinline__ void split_bf(float x, unsigned short& hi, unsigned short& lo) {
    __nv_bfloat16 h = __float2bfloat16(x);
    float r = x - __bfloat162float(h);
    __nv_bfloat16 l = __float2bfloat16(r);
    hi = __bfloat16_as_ushort(h);
    lo = __bfloat16_as_ushort(l);
}

__device__ __forceinline__ void mma16816(float* d, uint32_t a0, uint32_t a1, uint32_t a2, uint32_t a3,
                                         uint32_t b0, uint32_t b1) {
    asm volatile(
        "mma.sync.aligned.m16n8k16.row.col.f32.bf16.bf16.f32 "
        "{%0,%1,%2,%3}, {%4,%5,%6,%7}, {%8,%9}, {%0,%1,%2,%3};"
        : "+f"(d[0]), "+f"(d[1]), "+f"(d[2]), "+f"(d[3])
        : "r"(a0), "r"(a1), "r"(a2), "r"(a3), "r"(b0), "r"(b1));
}

// ---------------- dtype detect + merged prologue ----------------
__global__ void detect_kernel(const int* __restrict__ ei_words) {
    int is64 = 1;
    for (int i = 0; i < 256; i++)
        if (ei_words[2 * i + 1] != 0) { is64 = 0; break; }
    g_is64 = is64;
}
__global__ void prologue_kernel(const void* __restrict__ ei, const void* __restrict__ bat) {
    int i = blockIdx.x * blockDim.x + threadIdx.x;
    int is64 = g_is64;
    if (i < 2 * NEDGES)
        g_ei[i] = is64 ? (int)((const long long*)ei)[i] : ((const int*)ei)[i];
    if (i < NNODES) {
        g_bat[i] = is64 ? (int)((const long long*)bat)[i] : ((const int*)bat)[i];
        g_cnt[i] = 0;
        g_cnt2[i] = 0;
    }
    if (i < NGRAPHS * HID) g_pooled[i] = 0.f;
}

// ---------------- CSR build ----------------
__global__ void hist_kernel() {
    int e = blockIdx.x * blockDim.x + threadIdx.x;
    if (e < NEDGES) atomicAdd(&g_cnt[g_ei[NEDGES + e]], 1);
}

// multi-block scan: per-block exclusive scan + block totals
__global__ __launch_bounds__(1024) void scan1_kernel() {
    __shared__ int warpsum[32];
    int tid = threadIdx.x, lane = tid & 31, wid = tid >> 5;
    int i = blockIdx.x * 1024 + tid;
    int v = (i < NNODES) ? g_cnt[i] : 0;
    int s = v;
    #pragma unroll
    for (int off = 1; off < 32; off <<= 1) {
        int t = __shfl_up_sync(0xffffffffu, s, off);
        if (lane >= off) s += t;
    }
    if (lane == 31) warpsum[wid] = s;
    __syncthreads();
    if (wid == 0) {
        int ws = warpsum[lane];
        #pragma unroll
        for (int off = 1; off < 32; off <<= 1) {
            int t = __shfl_up_sync(0xffffffffu, ws, off);
            if (lane >= off) ws += t;
        }
        warpsum[lane] = ws;
    }
    __syncthreads();
    int woff = (wid > 0) ? warpsum[wid - 1] : 0;
    if (i < NNODES) g_rowptr[i] = s + woff - v;   // block-local exclusive
    if (tid == 1023) g_part[blockIdx.x] = s + woff;  // block total
}
// scan the 49 block totals (1 block, 64 threads)
__global__ void scan2_kernel() {
    __shared__ int sp[64];
    int tid = threadIdx.x;
    sp[tid] = (tid < SCAN_NB) ? g_part[tid] : 0;
    __syncthreads();
    if (tid == 0) {
        int acc = 0;
        #pragma unroll
        for (int b = 0; b < SCAN_NB; b++) { g_partoff[b] = acc; acc += sp[b]; }
        g_partoff[SCAN_NB] = acc;
    }
}
__global__ void scan3_kernel() {
    int i = blockIdx.x * blockDim.x + threadIdx.x;
    if (i < NNODES) g_rowptr[i] += g_partoff[i >> 10];
    if (i == 0) g_rowptr[NNODES] = g_partoff[SCAN_NB];
}

__global__ void scatter_kernel(const float* __restrict__ ea) {
    int e = blockIdx.x * blockDim.x + threadIdx.x;
    if (e >= NEDGES) return;
    int d = g_ei[NEDGES + e];
    int s = g_ei[e];
    int pos = g_rowptr[d] + atomicAdd(&g_cnt2[d], 1);
    g_srcPerm[pos] = s;
    float4* dst = (float4*)&g_eattr[(size_t)pos * FE];
    const float4* src = (const float4*)&ea[(size_t)e * FE];
    dst[0] = src[0]; dst[1] = src[1]; dst[2] = src[2]; dst[3] = src[3];
}

// ---------------- init GEMM: h = relu(x @ init_w + init_b), h0 = h ----------------
__global__ __launch_bounds__(256) void init_gemm_kernel(const float* __restrict__ X,
                                                        const float* __restrict__ W,
                                                        const float* __restrict__ B) {
    __shared__ float As[128][33];
    __shared__ float Ws[32][128];
    int tid = threadIdx.x;
    int row0 = blockIdx.x * 128;
    int tx = tid & 15, ty = tid >> 4;
    {
        int lr = tid >> 1, lc = (tid & 1) * 16;
        float4 v0, v1, v2, v3;
        if (row0 + lr < NNODES) {
            const float4* p = (const float4*)&X[(size_t)(row0 + lr) * FN + lc];
            v0 = p[0]; v1 = p[1]; v2 = p[2]; v3 = p[3];
        } else { v0 = make_float4(0.f, 0.f, 0.f, 0.f); v1 = v0; v2 = v0; v3 = v0; }
        As[lr][lc + 0] = v0.x; As[lr][lc + 1] = v0.y; As[lr][lc + 2] = v0.z; As[lr][lc + 3] = v0.w;
        As[lr][lc + 4] = v1.x; As[lr][lc + 5] = v1.y; As[lr][lc + 6] = v1.z; As[lr][lc + 7] = v1.w;
        As[lr][lc + 8] = v2.x; As[lr][lc + 9] = v2.y; As[lr][lc + 10] = v2.z; As[lr][lc + 11] = v2.w;
        As[lr][lc + 12] = v3.x; As[lr][lc + 13] = v3.y; As[lr][lc + 14] = v3.z; As[lr][lc + 15] = v3.w;
    }
    {
        int wk = tid >> 3, wc = (tid & 7) * 16;
        const float4* p = (const float4*)&W[(size_t)wk * HID + wc];
        float4 v0 = p[0], v1 = p[1], v2 = p[2], v3 = p[3];
        Ws[wk][wc + 0] = v0.x; Ws[wk][wc + 1] = v0.y; Ws[wk][wc + 2] = v0.z; Ws[wk][wc + 3] = v0.w;
        Ws[wk][wc + 4] = v1.x; Ws[wk][wc + 5] = v1.y; Ws[wk][wc + 6] = v1.z; Ws[wk][wc + 7] = v1.w;
        Ws[wk][wc + 8] = v2.x; Ws[wk][wc + 9] = v2.y; Ws[wk][wc + 10] = v2.z; Ws[wk][wc + 11] = v2.w;
        Ws[wk][wc + 12] = v3.x; Ws[wk][wc + 13] = v3.y; Ws[wk][wc + 14] = v3.z; Ws[wk][wc + 15] = v3.w;
    }
    __syncthreads();
    float acc[8][8];
    #pragma unroll
    for (int i = 0; i < 8; i++)
        #pragma unroll
        for (int j = 0; j < 8; j++) acc[i][j] = 0.f;
    #pragma unroll
    for (int kk = 0; kk < 32; kk++) {
        float a[8];
        #pragma unroll
        for (int i = 0; i < 8; i++) a[i] = As[ty * 8 + i][kk];
        float4 b0 = *(const float4*)&Ws[kk][tx * 8];
        float4 b1 = *(const float4*)&Ws[kk][tx * 8 + 4];
        float b[8] = {b0.x, b0.y, b0.z, b0.w, b1.x, b1.y, b1.z, b1.w};
        #pragma unroll
        for (int i = 0; i < 8; i++)
            #pragma unroll
            for (int j = 0; j < 8; j++) acc[i][j] += a[i] * b[j];
    }
    #pragma unroll
    for (int i = 0; i < 8; i++) {
        int r = row0 + ty * 8 + i;
        if (r < NNODES) {
            #pragma unroll
            for (int j = 0; j < 8; j++) {
                int c = tx * 8 + j;
                float v = acc[i][j] + B[c];
                v = v > 0.f ? v : 0.f;
                g_h[(size_t)r * HID + c] = v;
                g_h0[(size_t)r * HID + c] = v;
            }
        }
    }
}

// ================= edge GEMM: E = g_eattr(perm) @ W_d + b_d, bf16 out =================
#define EG_LDA 24
__global__ __launch_bounds__(256) void edge_gemm_kernel(const float* __restrict__ Wd,
                                                        const float* __restrict__ Bd) {
    __shared__ unsigned short sAhi[128 * EG_LDA], sAlo[128 * EG_LDA];
    __shared__ unsigned short sWhi[128 * EG_LDA], sWlo[128 * EG_LDA];
    __shared__ float sB[128];
    int tid = threadIdx.x, wid = tid >> 5, lane = tid & 31;
    int g = lane >> 2, t4 = lane & 3;
    int row0 = blockIdx.x * 128;
    int m0 = wid * 16;

    if (tid < 128) sB[tid] = Bd[tid];
    #pragma unroll
    for (int i = 0; i < 8; i++) {
        int idx = tid + 256 * i;
        int row = idx >> 4, k = idx & 15;
        float v = g_eattr[(size_t)(row0 + row) * FE + k];
        unsigned short h, l;
        split_bf(v, h, l);
        sAhi[row * EG_LDA + k] = h;
        sAlo[row * EG_LDA + k] = l;
    }
    #pragma unroll
    for (int i = 0; i < 8; i++) {
        int idx = tid + 256 * i;
        int k = idx >> 7, n = idx & 127;
        float v = Wd[idx];
        unsigned short h, l;
        split_bf(v, h, l);
        sWhi[n * EG_LDA + k] = h;
        sWlo[n * EG_LDA + k] = l;
    }
    __syncthreads();

    float d[16][4];
    #pragma unroll
    for (int j = 0; j < 16; j++)
        #pragma unroll
        for (int q = 0; q < 4; q++) d[j][q] = 0.f;

    uint32_t ah0 = *(uint32_t*)&sAhi[(m0 + g) * EG_LDA + 2 * t4];
    uint32_t ah1 = *(uint32_t*)&sAhi[(m0 + g + 8) * EG_LDA + 2 * t4];
    uint32_t ah2 = *(uint32_t*)&sAhi[(m0 + g) * EG_LDA + 2 * t4 + 8];
    uint32_t ah3 = *(uint32_t*)&sAhi[(m0 + g + 8) * EG_LDA + 2 * t4 + 8];
    uint32_t al0 = *(uint32_t*)&sAlo[(m0 + g) * EG_LDA + 2 * t4];
    uint32_t al1 = *(uint32_t*)&sAlo[(m0 + g + 8) * EG_LDA + 2 * t4];
    uint32_t al2 = *(uint32_t*)&sAlo[(m0 + g) * EG_LDA + 2 * t4 + 8];
    uint32_t al3 = *(uint32_t*)&sAlo[(m0 + g + 8) * EG_LDA + 2 * t4 + 8];
    #pragma unroll
    for (int j = 0; j < 16; j++) {
        int nrow = j * 8 + g;
        uint32_t bh0 = *(uint32_t*)&sWhi[nrow * EG_LDA + 2 * t4];
        uint32_t bh1 = *(uint32_t*)&sWhi[nrow * EG_LDA + 2 * t4 + 8];
        uint32_t bl0 = *(uint32_t*)&sWlo[nrow * EG_LDA + 2 * t4];
        uint32_t bl1 = *(uint32_t*)&sWlo[nrow * EG_LDA + 2 * t4 + 8];
        mma16816(d[j], ah0, ah1, ah2, ah3, bh0, bh1);
        mma16816(d[j], ah0, ah1, ah2, ah3, bl0, bl1);
        mma16816(d[j], al0, al1, al2, al3, bh0, bh1);
    }

    size_t e0 = (size_t)(row0 + m0 + g) * HID;
    size_t e1 = (size_t)(row0 + m0 + g + 8) * HID;
    #pragma unroll
    for (int j = 0; j < 16; j++) {
        int c = j * 8 + 2 * t4;
        float b0v = sB[c], b1v = sB[c + 1];
        unsigned short u00 = __bfloat16_as_ushort(__float2bfloat16(d[j][0] + b0v));
        unsigned short u01 = __bfloat16_as_ushort(__float2bfloat16(d[j][1] + b1v));
        unsigned short u10 = __bfloat16_as_ushort(__float2bfloat16(d[j][2] + b0v));
        unsigned short u11 = __bfloat16_as_ushort(__float2bfloat16(d[j][3] + b1v));
        *(uint32_t*)&g_E[e0 + c] = (uint32_t)u00 | ((uint32_t)u01 << 16);
        *(uint32_t*)&g_E[e1 + c] = (uint32_t)u10 | ((uint32_t)u11 << 16);
    }
}

// ---------------- aggregation: warp per node, 4-way edge unroll ----------------
__device__ __forceinline__ void aggr_step(float4& acc, int s, int e, int c4) {
    float4 hv = *(const float4*)&g_h[(size_t)s * HID + c4];
    uint2 ev = *(const uint2*)&g_E[(size_t)e * HID + c4];
    float e0 = __bfloat162float(__ushort_as_bfloat16((unsigned short)(ev.x & 0xFFFF)));
    float e1 = __bfloat162float(__ushort_as_bfloat16((unsigned short)(ev.x >> 16)));
    float e2 = __bfloat162float(__ushort_as_bfloat16((unsigned short)(ev.y & 0xFFFF)));
    float e3 = __bfloat162float(__ushort_as_bfloat16((unsigned short)(ev.y >> 16)));
    acc.x += fmaxf(hv.x + e0, 0.f);
    acc.y += fmaxf(hv.y + e1, 0.f);
    acc.z += fmaxf(hv.z + e2, 0.f);
    acc.w += fmaxf(hv.w + e3, 0.f);
}

__global__ __launch_bounds__(256) void aggr_kernel() {
    int wid = threadIdx.x >> 5, lane = threadIdx.x & 31;
    int n = blockIdx.x * 8 + wid;
    if (n >= NNODES) return;
    int c4 = lane * 4;
    int r0 = g_rowptr[n], r1 = g_rowptr[n + 1];
    float4 acc = *(const float4*)&g_h[(size_t)n * HID + c4];
    int e = r0;
    for (; e + 4 <= r1; e += 4) {
        int s0 = g_srcPerm[e];
        int s1 = g_srcPerm[e + 1];
        int s2 = g_srcPerm[e + 2];
        int s3 = g_srcPerm[e + 3];
        float4 h0 = *(const float4*)&g_h[(size_t)s0 * HID + c4];
        float4 h1 = *(const float4*)&g_h[(size_t)s1 * HID + c4];
        float4 h2 = *(const float4*)&g_h[(size_t)s2 * HID + c4];
        float4 h3 = *(const float4*)&g_h[(size_t)s3 * HID + c4];
        uint2 v0 = *(const uint2*)&g_E[(size_t)e * HID + c4];
        uint2 v1 = *(const uint2*)&g_E[(size_t)(e + 1) * HID + c4];
        uint2 v2 = *(const uint2*)&g_E[(size_t)(e + 2) * HID + c4];
        uint2 v3 = *(const uint2*)&g_E[(size_t)(e + 3) * HID + c4];
        #pragma unroll
        for (int q = 0; q < 4; q++) {
            float4 hv = (q == 0) ? h0 : (q == 1) ? h1 : (q == 2) ? h2 : h3;
            uint2 ev = (q == 0) ? v0 : (q == 1) ? v1 : (q == 2) ? v2 : v3;
            float e0 = __bfloat162float(__ushort_as_bfloat16((unsigned short)(ev.x & 0xFFFF)));
            float e1 = __bfloat162float(__ushort_as_bfloat16((unsigned short)(ev.x >> 16)));
            float e2 = __bfloat162float(__ushort_as_bfloat16((unsigned short)(ev.y & 0xFFFF)));
            float e3 = __bfloat162float(__ushort_as_bfloat16((unsigned short)(ev.y >> 16)));
            acc.x += fmaxf(hv.x + e0, 0.f);
            acc.y += fmaxf(hv.y + e1, 0.f);
            acc.z += fmaxf(hv.z + e2, 0.f);
            acc.w += fmaxf(hv.w + e3, 0.f);
        }
    }
    for (; e < r1; e++) aggr_step(acc, g_srcPerm[e], e, c4);
    *(float4*)&g_zin[(size_t)n * HID + c4] = acc;
}

// ================= fused node-MLP via mma.sync (bf16 split hi/lo) =================
#define LDH 136
#define SMF_B1 0
#define SMF_B2 512
#define SMF_AHI 1024
#define SMF_ALO (SMF_AHI + 128 * LDH * 2)
#define SMF_WHI (SMF_ALO + 128 * LDH * 2)
#define SMF_WLO (SMF_WHI + 128 * LDH * 2)
#define SMF_TOTAL (SMF_WLO + 128 * LDH * 2)

__global__ __launch_bounds__(256) void mlp_fused_kernel(
    const float* __restrict__ A, const float* __restrict__ W1, const float* __restrict__ B1,
    const float* __restrict__ W2, const float* __restrict__ B2,
    const float* __restrict__ H0, float* __restrict__ OUT)
{
    extern __shared__ __align__(16) char smem[];
    unsigned short* sAhi = (unsigned short*)(smem + SMF_AHI);
    unsigned short* sAlo = (unsigned short*)(smem + SMF_ALO);
    unsigned short* sWhi = (unsigned short*)(smem + SMF_WHI);
    unsigned short* sWlo = (unsigned short*)(smem + SMF_WLO);
    float* sB1 = (float*)(smem + SMF_B1);
    float* sB2 = (float*)(smem + SMF_B2);

    int tid = threadIdx.x, wid = tid >> 5, lane = tid & 31;
    int g = lane >> 2, t4 = lane & 3;
    int row0 = blockIdx.x * 128;
    int m0 = wid * 16;

    if (tid < 128) { sB1[tid] = B1[tid]; sB2[tid] = B2[tid]; }

    #pragma unroll
    for (int i = 0; i < 32; i++) {
        int idx2 = tid + 256 * i;
        int row = idx2 >> 6;
        int col = (idx2 & 63) * 2;
        int gr = row0 + row;
        float2 v = (gr < NNODES) ? *(const float2*)&A[(size_t)gr * HID + col]
                                 : make_float2(0.f, 0.f);
        unsigned short hx, lx, hy, ly;
        split_bf(v.x, hx, lx); split_bf(v.y, hy, ly);
        *(uint32_t*)&sAhi[row * LDH + col] = (uint32_t)hx | ((uint32_t)hy << 16);
        *(uint32_t*)&sAlo[row * LDH + col] = (uint32_t)lx | ((uint32_t)ly << 16);
    }
    #pragma unroll
    for (int i = 0; i < 64; i++) {
        int idx = tid + 256 * i;
        int k = idx >> 7;
        int n = idx & 127;
        float w = W1[idx];
        unsigned short h, l;
        split_bf(w, h, l);
        sWhi[n * LDH + k] = h;
        sWlo[n * LDH + k] = l;
    }
    __syncthreads();

    float d[16][4];
    #pragma unroll
    for (int j = 0; j < 16; j++)
        #pragma unroll
        for (int q = 0; q < 4; q++) d[j][q] = 0.f;

    #pragma unroll
    for (int ks = 0; ks < 8; ks++) {
        int k0 = ks * 16;
        uint32_t ah0 = *(uint32_t*)&sAhi[(m0 + g) * LDH + k0 + 2 * t4];
        uint32_t ah1 = *(uint32_t*)&sAhi[(m0 + g + 8) * LDH + k0 + 2 * t4];
        uint32_t ah2 = *(uint32_t*)&sAhi[(m0 + g) * LDH + k0 + 2 * t4 + 8];
        uint32_t ah3 = *(uint32_t*)&sAhi[(m0 + g + 8) * LDH + k0 + 2 * t4 + 8];
        uint32_t al0 = *(uint32_t*)&sAlo[(m0 + g) * LDH + k0 + 2 * t4];
        uint32_t al1 = *(uint32_t*)&sAlo[(m0 + g + 8) * LDH + k0 + 2 * t4];
        uint32_t al2 = *(uint32_t*)&sAlo[(m0 + g) * LDH + k0 + 2 * t4 + 8];
        uint32_t al3 = *(uint32_t*)&sAlo[(m0 + g + 8) * LDH + k0 + 2 * t4 + 8];
        #pragma unroll
        for (int j = 0; j < 16; j++) {
            int nrow = j * 8 + g;
            uint32_t bh0 = *(uint32_t*)&sWhi[nrow * LDH + k0 + 2 * t4];
            uint32_t bh1 = *(uint32_t*)&sWhi[nrow * LDH + k0 + 2 * t4 + 8];
            uint32_t bl0 = *(uint32_t*)&sWlo[nrow * LDH + k0 + 2 * t4];
            uint32_t bl1 = *(uint32_t*)&sWlo[nrow * LDH + k0 + 2 * t4 + 8];
            mma16816(d[j], ah0, ah1, ah2, ah3, bh0, bh1);
            mma16816(d[j], ah0, ah1, ah2, ah3, bl0, bl1);
            mma16816(d[j], al0, al1, al2, al3, bh0, bh1);
        }
    }

    #pragma unroll
    for (int j = 0; j < 16; j++) {
        int c = j * 8 + 2 * t4;
        float b0v = sB1[c], b1v = sB1[c + 1];
        float v00 = d[j][0] + b0v, v01 = d[j][1] + b1v;
        float v10 = d[j][2] + b0v, v11 = d[j][3] + b1v;
        v00 = v00 > 0.f ? v00 : 0.f; v01 = v01 > 0.f ? v01 : 0.f;
        v10 = v10 > 0.f ? v10 : 0.f; v11 = v11 > 0.f ? v11 : 0.f;
        unsigned short h00, l00, h01, l01, h10, l10, h11, l11;
        split_bf(v00, h00, l00); split_bf(v01, h01, l01);
        split_bf(v10, h10, l10); split_bf(v11, h11, l11);
        *(uint32_t*)&sAhi[(m0 + g) * LDH + c]     = (uint32_t)h00 | ((uint32_t)h01 << 16);
        *(uint32_t*)&sAlo[(m0 + g) * LDH + c]     = (uint32_t)l00 | ((uint32_t)l01 << 16);
        *(uint32_t*)&sAhi[(m0 + g + 8) * LDH + c] = (uint32_t)h10 | ((uint32_t)h11 << 16);
        *(uint32_t*)&sAlo[(m0 + g + 8) * LDH + c] = (uint32_t)l10 | ((uint32_t)l11 << 16);
    }
    __syncthreads();
    #pragma unroll
    for (int i = 0; i < 64; i++) {
        int idx = tid + 256 * i;
        int k = idx >> 7;
        int n = idx & 127;
        float w = W2[idx];
        unsigned short h, l;
        split_bf(w, h, l);
        sWhi[n * LDH + k] = h;
        sWlo[n * LDH + k] = l;
    }
    __syncthreads();

    #pragma unroll
    for (int j = 0; j < 16; j++)
        #pragma unroll
        for (int q = 0; q < 4; q++) d[j][q] = 0.f;

    #pragma unroll
    for (int ks = 0; ks < 8; ks++) {
        int k0 = ks * 16;
        uint32_t ah0 = *(uint32_t*)&sAhi[(m0 + g) * LDH + k0 + 2 * t4];
        uint32_t ah1 = *(uint32_t*)&sAhi[(m0 + g + 8) * LDH + k0 + 2 * t4];
        uint32_t ah2 = *(uint32_t*)&sAhi[(m0 + g) * LDH + k0 + 2 * t4 + 8];
        uint32_t ah3 = *(uint32_t*)&sAhi[(m0 + g + 8) * LDH + k0 + 2 * t4 + 8];
        uint32_t al0 = *(uint32_t*)&sAlo[(m0 + g) * LDH + k0 + 2 * t4];
        uint32_t al1 = *(uint32_t*)&sAlo[(m0 + g + 8) * LDH + k0 + 2 * t4];
        uint32_t al2 = *(uint32_t*)&sAlo[(m0 + g) * LDH + k0 + 2 * t4 + 8];
        uint32_t al3 = *(uint32_t*)&sAlo[(m0 + g + 8) * LDH + k0 + 2 * t4 + 8];
        #pragma unroll
        for (int j = 0; j < 16; j++) {
            int nrow = j * 8 + g;
            uint32_t bh0 = *(uint32_t*)&sWhi[nrow * LDH + k0 + 2 * t4];
            uint32_t bh1 = *(uint32_t*)&sWhi[nrow * LDH + k0 + 2 * t4 + 8];
            uint32_t bl0 = *(uint32_t*)&sWlo[nrow * LDH + k0 + 2 * t4];
            uint32_t bl1 = *(uint32_t*)&sWlo[nrow * LDH + k0 + 2 * t4 + 8];
            mma16816(d[j], ah0, ah1, ah2, ah3, bh0, bh1);
            mma16816(d[j], ah0, ah1, ah2, ah3, bl0, bl1);
            mma16816(d[j], al0, al1, al2, al3, bh0, bh1);
        }
    }

    {
        int gr0 = row0 + m0 + g;
        int gr1 = gr0 + 8;
        #pragma unroll
        for (int j = 0; j < 16; j++) {
            int c = j * 8 + 2 * t4;
            float b0v = sB2[c], b1v = sB2[c + 1];
            if (gr0 < NNODES) {
                float2 h0v = *(const float2*)&H0[(size_t)gr0 * HID + c];
                float2 o;
                o.x = d[j][0] + b0v + h0v.x;
                o.y = d[j][1] + b1v + h0v.y;
                o.x = o.x > 0.f ? o.x : 0.f;
                o.y = o.y > 0.f ? o.y : 0.f;
                *(float2*)&OUT[(size_t)gr0 * HID + c] = o;
            }
            if (gr1 < NNODES) {
                float2 h0v = *(const float2*)&H0[(size_t)gr1 * HID + c];
                float2 o;
                o.x = d[j][2] + b0v + h0v.x;
                o.y = d[j][3] + b1v + h0v.y;
                o.x = o.x > 0.f ? o.x : 0.f;
                o.y = o.y > 0.f ? o.y : 0.f;
                *(float2*)&OUT[(size_t)gr1 * HID + c] = o;
            }
        }
    }
}

// ---------------- pooling (batch is sorted) ----------------
__global__ void pool_kernel() {
    const int CH = 256;
    int start = blockIdx.x * CH;
    if (start >= NNODES) return;
    int end = min(start + CH, NNODES);
    int tid = threadIdx.x;
    int gcur = g_bat[start];
    float acc = 0.f;
    for (int n = start; n < end; n++) {
        int b = g_bat[n];
        if (b != gcur) {
            atomicAdd(&g_pooled[gcur * HID + tid], acc);
            acc = 0.f;
            gcur = b;
        }
        acc += g_h[(size_t)n * HID + tid];
    }
    atomicAdd(&g_pooled[gcur * HID + tid], acc);
}

__global__ void final_kernel(const float* __restrict__ fw, const float* __restrict__ fb,
                             float* __restrict__ out) {
    int g = threadIdx.x;
    float s = fb[0];
    #pragma unroll 8
    for (int c = 0; c < HID; c++) s += g_pooled[g * HID + c] * fw[c];
    out[g] = s;
}

// ---------------- launch ----------------
extern "C" void kernel_launch(void* const* d_in, const int* in_sizes, int n_in,
                              void* d_out, int out_size) {
    const float* x       = (const float*)d_in[0];
    const void*  ei      = d_in[1];
    const float* eattr   = (const float*)d_in[2];
    const void*  bat     = d_in[3];
    const float* init_w  = (const float*)d_in[4];
    const float* init_b  = (const float*)d_in[5];
    const float* edge_w  = (const float*)d_in[6];
    const float* edge_b  = (const float*)d_in[7];
    const float* mlp_w1  = (const float*)d_in[8];
    const float* mlp_b1  = (const float*)d_in[9];
    const float* mlp_w2  = (const float*)d_in[10];
    const float* mlp_b2  = (const float*)d_in[11];
    const float* ffn_w   = (const float*)d_in[12];
    const float* ffn_b   = (const float*)d_in[13];
    float* out = (float*)d_out;

    float *p_h = 0, *p_h0 = 0, *p_zin = 0;
    cudaGetSymbolAddress((void**)&p_h,   g_h);
    cudaGetSymbolAddress((void**)&p_h0,  g_h0);
    cudaGetSymbolAddress((void**)&p_zin, g_zin);

    cudaFuncSetAttribute(mlp_fused_kernel, cudaFuncAttributeMaxDynamicSharedMemorySize, SMF_TOTAL);

    const int EBLK = (NEDGES + 255) / 256;
    const int NBLK = (NNODES + 255) / 256;
    const int GBLK = (NNODES + 127) / 128;
    const int PBLK = (2 * NEDGES + 255) / 256;

    detect_kernel<<<1, 1>>>((const int*)ei);
    prologue_kernel<<<PBLK, 256>>>(ei, bat);
    hist_kernel<<<EBLK, 256>>>();
    scan1_kernel<<<SCAN_NB, 1024>>>();
    scan2_kernel<<<1, 64>>>();
    scan3_kernel<<<NBLK, 256>>>();
    scatter_kernel<<<EBLK, 256>>>(eattr);

    init_gemm_kernel<<<GBLK, 256>>>(x, init_w, init_b);

    for (int d = 0; d < DEPTH; d++) {
        edge_gemm_kernel<<<NEDGES / 128, 256>>>(edge_w + (size_t)d * FE * HID,
                                                edge_b + (size_t)d * HID);
        aggr_kernel<<<(NNODES + 7) / 8, 256>>>();
        mlp_fused_kernel<<<GBLK, 256, SMF_TOTAL>>>(
            p_zin, mlp_w1 + (size_t)d * HID * HID, mlp_b1 + (size_t)d * HID,
            mlp_w2 + (size_t)d * HID * HID, mlp_b2 + (size_t)d * HID, p_h0, p_h);
    }

    pool_kernel<<<(NNODES + 255) / 256, 128>>>();
    final_kernel<<<1, 128>>>(ffn_w, ffn_b, out);
}

// round 14
// speedup vs baseline: 1.9644x; 1.0356x over previous
#include <cuda_runtime.h>
#include <cuda_bf16.h>
#include <cstdint>

#define NNODES 50000
#define NEDGES 800000
#define FN 32
#define FE 16
#define HID 128
#define DEPTH 4
#define NGRAPHS 128
#define SCAN_NB 49   // ceil(50000/1024)

// ---------------- scratch (device globals: allocation-free) ----------------
__device__ float g_h[NNODES * HID];
__device__ float g_h0[NNODES * HID];
__device__ float g_zin[NNODES * HID];
__device__ int   g_cnt[NNODES];
__device__ int   g_cnt2[NNODES];
__device__ int   g_rowptr[NNODES + 1];
__device__ int   g_part[SCAN_NB];
__device__ int   g_partoff[SCAN_NB + 1];
__device__ int   g_srcPerm[NEDGES];
__device__ __align__(16) float g_eattr[NEDGES * FE];
__device__ __align__(16) unsigned short g_E[(size_t)NEDGES * HID];
__device__ float g_pooled[NGRAPHS * HID];
__device__ int   g_ei[2 * NEDGES];
__device__ int   g_bat[NNODES];
__device__ int   g_is64;

__device__ __forceinline__ void split_bf(float x, unsigned short& hi, unsigned short& lo) {
    __nv_bfloat16 h = __float2bfloat16(x);
    float r = x - __bfloat162float(h);
    __nv_bfloat16 l = __float2bfloat16(r);
    hi = __bfloat16_as_ushort(h);
    lo = __bfloat16_as_ushort(l);
}

__device__ __forceinline__ void mma16816(float* d, uint32_t a0, uint32_t a1, uint32_t a2, uint32_t a3,
                                         uint32_t b0, uint32_t b1) {
    asm volatile(
        "mma.sync.aligned.m16n8k16.row.col.f32.bf16.bf16.f32 "
        "{%0,%1,%2,%3}, {%4,%5,%6,%7}, {%8,%9}, {%0,%1,%2,%3};"
        : "+f"(d[0]), "+f"(d[1]), "+f"(d[2]), "+f"(d[3])
        : "r"(a0), "r"(a1), "r"(a2), "r"(a3), "r"(b0), "r"(b1));
}

// ---------------- dtype detect (parallel) + merged prologue ----------------
__global__ void detect_kernel(const int* __restrict__ ei_words) {
    // int64 node ids < 50000 -> every odd 32-bit word of the first 256 entries is 0.
    __shared__ int nz[8];
    int tid = threadIdx.x;            // 256 threads
    int w = ei_words[2 * tid + 1];
    unsigned int b = __ballot_sync(0xffffffffu, w != 0);
    if ((tid & 31) == 0) nz[tid >> 5] = (b != 0);
    __syncthreads();
    if (tid == 0) {
        int any = 0;
        #pragma unroll
        for (int i = 0; i < 8; i++) any |= nz[i];
        g_is64 = any ? 0 : 1;
    }
}
__global__ void prologue_kernel(const void* __restrict__ ei, const void* __restrict__ bat) {
    int i = blockIdx.x * blockDim.x + threadIdx.x;
    int is64 = g_is64;
    if (i < 2 * NEDGES)
        g_ei[i] = is64 ? (int)((const long long*)ei)[i] : ((const int*)ei)[i];
    if (i < NNODES) {
        g_bat[i] = is64 ? (int)((const long long*)bat)[i] : ((const int*)bat)[i];
        g_cnt[i] = 0;
        g_cnt2[i] = 0;
    }
    if (i < NGRAPHS * HID) g_pooled[i] = 0.f;
}

// ---------------- CSR build ----------------
__global__ void hist_kernel() {
    int e = blockIdx.x * blockDim.x + threadIdx.x;
    if (e < NEDGES) atomicAdd(&g_cnt[g_ei[NEDGES + e]], 1);
}

__global__ __launch_bounds__(1024) void scan1_kernel() {
    __shared__ int warpsum[32];
    int tid = threadIdx.x, lane = tid & 31, wid = tid >> 5;
    int i = blockIdx.x * 1024 + tid;
    int v = (i < NNODES) ? g_cnt[i] : 0;
    int s = v;
    #pragma unroll
    for (int off = 1; off < 32; off <<= 1) {
        int t = __shfl_up_sync(0xffffffffu, s, off);
        if (lane >= off) s += t;
    }
    if (lane == 31) warpsum[wid] = s;
    __syncthreads();
    if (wid == 0) {
        int ws = warpsum[lane];
        #pragma unroll
        for (int off = 1; off < 32; off <<= 1) {
            int t = __shfl_up_sync(0xffffffffu, ws, off);
            if (lane >= off) ws += t;
        }
        warpsum[lane] = ws;
    }
    __syncthreads();
    int woff = (wid > 0) ? warpsum[wid - 1] : 0;
    if (i < NNODES) g_rowptr[i] = s + woff - v;
    if (tid == 1023) g_part[blockIdx.x] = s + woff;
}
__global__ void scan2_kernel() {
    __shared__ int sp[64];
    int tid = threadIdx.x;
    sp[tid] = (tid < SCAN_NB) ? g_part[tid] : 0;
    __syncthreads();
    if (tid == 0) {
        int acc = 0;
        #pragma unroll
        for (int b = 0; b < SCAN_NB; b++) { g_partoff[b] = acc; acc += sp[b]; }
        g_partoff[SCAN_NB] = acc;
    }
}
__global__ void scan3_kernel() {
    int i = blockIdx.x * blockDim.x + threadIdx.x;
    if (i < NNODES) g_rowptr[i] += g_partoff[i >> 10];
    if (i == 0) g_rowptr[NNODES] = g_partoff[SCAN_NB];
}

__global__ void scatter_kernel(const float* __restrict__ ea) {
    int e = blockIdx.x * blockDim.x + threadIdx.x;
    if (e >= NEDGES) return;
    int d = g_ei[NEDGES + e];
    int s = g_ei[e];
    int pos = g_rowptr[d] + atomicAdd(&g_cnt2[d], 1);
    g_srcPerm[pos] = s;
    float4* dst = (float4*)&g_eattr[(size_t)pos * FE];
    const float4* src = (const float4*)&ea[(size_t)e * FE];
    dst[0] = src[0]; dst[1] = src[1]; dst[2] = src[2]; dst[3] = src[3];
}

// ---------------- init GEMM: h = relu(x @ init_w + init_b), h0 = h ----------------
__global__ __launch_bounds__(256) void init_gemm_kernel(const float* __restrict__ X,
                                                        const float* __restrict__ W,
                                                        const float* __restrict__ B) {
    __shared__ float As[128][33];
    __shared__ float Ws[32][128];
    int tid = threadIdx.x;
    int row0 = blockIdx.x * 128;
    int tx = tid & 15, ty = tid >> 4;
    {
        int lr = tid >> 1, lc = (tid & 1) * 16;
        float4 v0, v1, v2, v3;
        if (row0 + lr < NNODES) {
            const float4* p = (const float4*)&X[(size_t)(row0 + lr) * FN + lc];
            v0 = p[0]; v1 = p[1]; v2 = p[2]; v3 = p[3];
        } else { v0 = make_float4(0.f, 0.f, 0.f, 0.f); v1 = v0; v2 = v0; v3 = v0; }
        As[lr][lc + 0] = v0.x; As[lr][lc + 1] = v0.y; As[lr][lc + 2] = v0.z; As[lr][lc + 3] = v0.w;
        As[lr][lc + 4] = v1.x; As[lr][lc + 5] = v1.y; As[lr][lc + 6] = v1.z; As[lr][lc + 7] = v1.w;
        As[lr][lc + 8] = v2.x; As[lr][lc + 9] = v2.y; As[lr][lc + 10] = v2.z; As[lr][lc + 11] = v2.w;
        As[lr][lc + 12] = v3.x; As[lr][lc + 13] = v3.y; As[lr][lc + 14] = v3.z; As[lr][lc + 15] = v3.w;
    }
    {
        int wk = tid >> 3, wc = (tid & 7) * 16;
        const float4* p = (const float4*)&W[(size_t)wk * HID + wc];
        float4 v0 = p[0], v1 = p[1], v2 = p[2], v3 = p[3];
        Ws[wk][wc + 0] = v0.x; Ws[wk][wc + 1] = v0.y; Ws[wk][wc + 2] = v0.z; Ws[wk][wc + 3] = v0.w;
        Ws[wk][wc + 4] = v1.x; Ws[wk][wc + 5] = v1.y; Ws[wk][wc + 6] = v1.z; Ws[wk][wc + 7] = v1.w;
        Ws[wk][wc + 8] = v2.x; Ws[wk][wc + 9] = v2.y; Ws[wk][wc + 10] = v2.z; Ws[wk][wc + 11] = v2.w;
        Ws[wk][wc + 12] = v3.x; Ws[wk][wc + 13] = v3.y; Ws[wk][wc + 14] = v3.z; Ws[wk][wc + 15] = v3.w;
    }
    __syncthreads();
    float acc[8][8];
    #pragma unroll
    for (int i = 0; i < 8; i++)
        #pragma unroll
        for (int j = 0; j < 8; j++) acc[i][j] = 0.f;
    #pragma unroll
    for (int kk = 0; kk < 32; kk++) {
        float a[8];
        #pragma unroll
        for (int i = 0; i < 8; i++) a[i] = As[ty * 8 + i][kk];
        float4 b0 = *(const float4*)&Ws[kk][tx * 8];
        float4 b1 = *(const float4*)&Ws[kk][tx * 8 + 4];
        float b[8] = {b0.x, b0.y, b0.z, b0.w, b1.x, b1.y, b1.z, b1.w};
        #pragma unroll
        for (int i = 0; i < 8; i++)
            #pragma unroll
            for (int j = 0; j < 8; j++) acc[i][j] += a[i] * b[j];
    }
    #pragma unroll
    for (int i = 0; i < 8; i++) {
        int r = row0 + ty * 8 + i;
        if (r < NNODES) {
            #pragma unroll
            for (int j = 0; j < 8; j++) {
                int c = tx * 8 + j;
                float v = acc[i][j] + B[c];
                v = v > 0.f ? v : 0.f;
                g_h[(size_t)r * HID + c] = v;
                g_h0[(size_t)r * HID + c] = v;
            }
        }
    }
}

// ================= edge GEMM: E = g_eattr(perm) @ W_d + b_d, bf16 out (streaming stores) =================
#define EG_LDA 24
__global__ __launch_bounds__(256) void edge_gemm_kernel(const float* __restrict__ Wd,
                                                        const float* __restrict__ Bd) {
    __shared__ unsigned short sAhi[128 * EG_LDA], sAlo[128 * EG_LDA];
    __shared__ unsigned short sWhi[128 * EG_LDA], sWlo[128 * EG_LDA];
    __shared__ float sB[128];
    int tid = threadIdx.x, wid = tid >> 5, lane = tid & 31;
    int g = lane >> 2, t4 = lane & 3;
    int row0 = blockIdx.x * 128;
    int m0 = wid * 16;

    if (tid < 128) sB[tid] = Bd[tid];
    #pragma unroll
    for (int i = 0; i < 8; i++) {
        int idx = tid + 256 * i;
        int row = idx >> 4, k = idx & 15;
        float v = g_eattr[(size_t)(row0 + row) * FE + k];
        unsigned short h, l;
        split_bf(v, h, l);
        sAhi[row * EG_LDA + k] = h;
        sAlo[row * EG_LDA + k] = l;
    }
    #pragma unroll
    for (int i = 0; i < 8; i++) {
        int idx = tid + 256 * i;
        int k = idx >> 7, n = idx & 127;
        float v = Wd[idx];
        unsigned short h, l;
        split_bf(v, h, l);
        sWhi[n * EG_LDA + k] = h;
        sWlo[n * EG_LDA + k] = l;
    }
    __syncthreads();

    float d[16][4];
    #pragma unroll
    for (int j = 0; j < 16; j++)
        #pragma unroll
        for (int q = 0; q < 4; q++) d[j][q] = 0.f;

    uint32_t ah0 = *(uint32_t*)&sAhi[(m0 + g) * EG_LDA + 2 * t4];
    uint32_t ah1 = *(uint32_t*)&sAhi[(m0 + g + 8) * EG_LDA + 2 * t4];
    uint32_t ah2 = *(uint32_t*)&sAhi[(m0 + g) * EG_LDA + 2 * t4 + 8];
    uint32_t ah3 = *(uint32_t*)&sAhi[(m0 + g + 8) * EG_LDA + 2 * t4 + 8];
    uint32_t al0 = *(uint32_t*)&sAlo[(m0 + g) * EG_LDA + 2 * t4];
    uint32_t al1 = *(uint32_t*)&sAlo[(m0 + g + 8) * EG_LDA + 2 * t4];
    uint32_t al2 = *(uint32_t*)&sAlo[(m0 + g) * EG_LDA + 2 * t4 + 8];
    uint32_t al3 = *(uint32_t*)&sAlo[(m0 + g + 8) * EG_LDA + 2 * t4 + 8];
    #pragma unroll
    for (int j = 0; j < 16; j++) {
        int nrow = j * 8 + g;
        uint32_t bh0 = *(uint32_t*)&sWhi[nrow * EG_LDA + 2 * t4];
        uint32_t bh1 = *(uint32_t*)&sWhi[nrow * EG_LDA + 2 * t4 + 8];
        uint32_t bl0 = *(uint32_t*)&sWlo[nrow * EG_LDA + 2 * t4];
        uint32_t bl1 = *(uint32_t*)&sWlo[nrow * EG_LDA + 2 * t4 + 8];
        mma16816(d[j], ah0, ah1, ah2, ah3, bh0, bh1);
        mma16816(d[j], ah0, ah1, ah2, ah3, bl0, bl1);
        mma16816(d[j], al0, al1, al2, al3, bh0, bh1);
    }

    size_t e0 = (size_t)(row0 + m0 + g) * HID;
    size_t e1 = (size_t)(row0 + m0 + g + 8) * HID;
    #pragma unroll
    for (int j = 0; j < 16; j++) {
        int c = j * 8 + 2 * t4;
        float b0v = sB[c], b1v = sB[c + 1];
        unsigned short u00 = __bfloat16_as_ushort(__float2bfloat16(d[j][0] + b0v));
        unsigned short u01 = __bfloat16_as_ushort(__float2bfloat16(d[j][1] + b1v));
        unsigned short u10 = __bfloat16_as_ushort(__float2bfloat16(d[j][2] + b0v));
        unsigned short u11 = __bfloat16_as_ushort(__float2bfloat16(d[j][3] + b1v));
        __stcs((unsigned int*)&g_E[e0 + c], (unsigned int)u00 | ((unsigned int)u01 << 16));
        __stcs((unsigned int*)&g_E[e1 + c], (unsigned int)u10 | ((unsigned int)u11 << 16));
    }
}

// ---------------- aggregation: warp per node, 4-way unroll, streaming E reads ----------------
__device__ __forceinline__ void aggr_step(float4& acc, int s, int e, int c4) {
    float4 hv = *(const float4*)&g_h[(size_t)s * HID + c4];
    uint2 ev = __ldcs((const uint2*)&g_E[(size_t)e * HID + c4]);
    float e0 = __bfloat162float(__ushort_as_bfloat16((unsigned short)(ev.x & 0xFFFF)));
    float e1 = __bfloat162float(__ushort_as_bfloat16((unsigned short)(ev.x >> 16)));
    float e2 = __bfloat162float(__ushort_as_bfloat16((unsigned short)(ev.y & 0xFFFF)));
    float e3 = __bfloat162float(__ushort_as_bfloat16((unsigned short)(ev.y >> 16)));
    acc.x += fmaxf(hv.x + e0, 0.f);
    acc.y += fmaxf(hv.y + e1, 0.f);
    acc.z += fmaxf(hv.z + e2, 0.f);
    acc.w += fmaxf(hv.w + e3, 0.f);
}

__global__ __launch_bounds__(256) void aggr_kernel() {
    int wid = threadIdx.x >> 5, lane = threadIdx.x & 31;
    int n = blockIdx.x * 8 + wid;
    if (n >= NNODES) return;
    int c4 = lane * 4;
    int r0 = g_rowptr[n], r1 = g_rowptr[n + 1];
    float4 acc = *(const float4*)&g_h[(size_t)n * HID + c4];
    int e = r0;
    for (; e + 4 <= r1; e += 4) {
        int s0 = g_srcPerm[e];
        int s1 = g_srcPerm[e + 1];
        int s2 = g_srcPerm[e + 2];
        int s3 = g_srcPerm[e + 3];
        float4 h0 = *(const float4*)&g_h[(size_t)s0 * HID + c4];
        float4 h1 = *(const float4*)&g_h[(size_t)s1 * HID + c4];
        float4 h2 = *(const float4*)&g_h[(size_t)s2 * HID + c4];
        float4 h3 = *(const float4*)&g_h[(size_t)s3 * HID + c4];
        uint2 v0 = __ldcs((const uint2*)&g_E[(size_t)e * HID + c4]);
        uint2 v1 = __ldcs((const uint2*)&g_E[(size_t)(e + 1) * HID + c4]);
        uint2 v2 = __ldcs((const uint2*)&g_E[(size_t)(e + 2) * HID + c4]);
        uint2 v3 = __ldcs((const uint2*)&g_E[(size_t)(e + 3) * HID + c4]);
        #pragma unroll
        for (int q = 0; q < 4; q++) {
            float4 hv = (q == 0) ? h0 : (q == 1) ? h1 : (q == 2) ? h2 : h3;
            uint2 ev = (q == 0) ? v0 : (q == 1) ? v1 : (q == 2) ? v2 : v3;
            float e0 = __bfloat162float(__ushort_as_bfloat16((unsigned short)(ev.x & 0xFFFF)));
            float e1 = __bfloat162float(__ushort_as_bfloat16((unsigned short)(ev.x >> 16)));
            float e2 = __bfloat162float(__ushort_as_bfloat16((unsigned short)(ev.y & 0xFFFF)));
            float e3 = __bfloat162float(__ushort_as_bfloat16((unsigned short)(ev.y >> 16)));
            acc.x += fmaxf(hv.x + e0, 0.f);
            acc.y += fmaxf(hv.y + e1, 0.f);
            acc.z += fmaxf(hv.z + e2, 0.f);
            acc.w += fmaxf(hv.w + e3, 0.f);
        }
    }
    for (; e < r1; e++) aggr_step(acc, g_srcPerm[e], e, c4);
    *(float4*)&g_zin[(size_t)n * HID + c4] = acc;
}

// ================= fused node-MLP via mma.sync (bf16 split hi/lo) =================
#define LDH 136
#define SMF_B1 0
#define SMF_B2 512
#define SMF_AHI 1024
#define SMF_ALO (SMF_AHI + 128 * LDH * 2)
#define SMF_WHI (SMF_ALO + 128 * LDH * 2)
#define SMF_WLO (SMF_WHI + 128 * LDH * 2)
#define SMF_TOTAL (SMF_WLO + 128 * LDH * 2)

__global__ __launch_bounds__(256) void mlp_fused_kernel(
    const float* __restrict__ A, const float* __restrict__ W1, const float* __restrict__ B1,
    const float* __restrict__ W2, const float* __restrict__ B2,
    const float* __restrict__ H0, float* __restrict__ OUT)
{
    extern __shared__ __align__(16) char smem[];
    unsigned short* sAhi = (unsigned short*)(smem + SMF_AHI);
    unsigned short* sAlo = (unsigned short*)(smem + SMF_ALO);
    unsigned short* sWhi = (unsigned short*)(smem + SMF_WHI);
    unsigned short* sWlo = (unsigned short*)(smem + SMF_WLO);
    float* sB1 = (float*)(smem + SMF_B1);
    float* sB2 = (float*)(smem + SMF_B2);

    int tid = threadIdx.x, wid = tid >> 5, lane = tid & 31;
    int g = lane >> 2, t4 = lane & 3;
    int row0 = blockIdx.x * 128;
    int m0 = wid * 16;

    if (tid < 128) { sB1[tid] = B1[tid]; sB2[tid] = B2[tid]; }

    #pragma unroll
    for (int i = 0; i < 32; i++) {
        int idx2 = tid + 256 * i;
        int row = idx2 >> 6;
        int col = (idx2 & 63) * 2;
        int gr = row0 + row;
        float2 v = (gr < NNODES) ? *(const float2*)&A[(size_t)gr * HID + col]
                                 : make_float2(0.f, 0.f);
        unsigned short hx, lx, hy, ly;
        split_bf(v.x, hx, lx); split_bf(v.y, hy, ly);
        *(uint32_t*)&sAhi[row * LDH + col] = (uint32_t)hx | ((uint32_t)hy << 16);
        *(uint32_t*)&sAlo[row * LDH + col] = (uint32_t)lx | ((uint32_t)ly << 16);
    }
    #pragma unroll
    for (int i = 0; i < 64; i++) {
        int idx = tid + 256 * i;
        int k = idx >> 7;
        int n = idx & 127;
        float w = W1[idx];
        unsigned short h, l;
        split_bf(w, h, l);
        sWhi[n * LDH + k] = h;
        sWlo[n * LDH + k] = l;
    }
    __syncthreads();

    float d[16][4];
    #pragma unroll
    for (int j = 0; j < 16; j++)
        #pragma unroll
        for (int q = 0; q < 4; q++) d[j][q] = 0.f;

    #pragma unroll
    for (int ks = 0; ks < 8; ks++) {
        int k0 = ks * 16;
        uint32_t ah0 = *(uint32_t*)&sAhi[(m0 + g) * LDH + k0 + 2 * t4];
        uint32_t ah1 = *(uint32_t*)&sAhi[(m0 + g + 8) * LDH + k0 + 2 * t4];
        uint32_t ah2 = *(uint32_t*)&sAhi[(m0 + g) * LDH + k0 + 2 * t4 + 8];
        uint32_t ah3 = *(uint32_t*)&sAhi[(m0 + g + 8) * LDH + k0 + 2 * t4 + 8];
        uint32_t al0 = *(uint32_t*)&sAlo[(m0 + g) * LDH + k0 + 2 * t4];
        uint32_t al1 = *(uint32_t*)&sAlo[(m0 + g + 8) * LDH + k0 + 2 * t4];
        uint32_t al2 = *(uint32_t*)&sAlo[(m0 + g) * LDH + k0 + 2 * t4 + 8];
        uint32_t al3 = *(uint32_t*)&sAlo[(m0 + g + 8) * LDH + k0 + 2 * t4 + 8];
        #pragma unroll
        for (int j = 0; j < 16; j++) {
            int nrow = j * 8 + g;
            uint32_t bh0 = *(uint32_t*)&sWhi[nrow * LDH + k0 + 2 * t4];
            uint32_t bh1 = *(uint32_t*)&sWhi[nrow * LDH + k0 + 2 * t4 + 8];
            uint32_t bl0 = *(uint32_t*)&sWlo[nrow * LDH + k0 + 2 * t4];
            uint32_t bl1 = *(uint32_t*)&sWlo[nrow * LDH + k0 + 2 * t4 + 8];
            mma16816(d[j], ah0, ah1, ah2, ah3, bh0, bh1);
            mma16816(d[j], ah0, ah1, ah2, ah3, bl0, bl1);
            mma16816(d[j], al0, al1, al2, al3, bh0, bh1);
        }
    }

    #pragma unroll
    for (int j = 0; j < 16; j++) {
        int c = j * 8 + 2 * t4;
        float b0v = sB1[c], b1v = sB1[c + 1];
        float v00 = d[j][0] + b0v, v01 = d[j][1] + b1v;
        float v10 = d[j][2] + b0v, v11 = d[j][3] + b1v;
        v00 = v00 > 0.f ? v00 : 0.f; v01 = v01 > 0.f ? v01 : 0.f;
        v10 = v10 > 0.f ? v10 : 0.f; v11 = v11 > 0.f ? v11 : 0.f;
        unsigned short h00, l00, h01, l01, h10, l10, h11, l11;
        split_bf(v00, h00, l00); split_bf(v01, h01, l01);
        split_bf(v10, h10, l10); split_bf(v11, h11, l11);
        *(uint32_t*)&sAhi[(m0 + g) * LDH + c]     = (uint32_t)h00 | ((uint32_t)h01 << 16);
        *(uint32_t*)&sAlo[(m0 + g) * LDH + c]     = (uint32_t)l00 | ((uint32_t)l01 << 16);
        *(uint32_t*)&sAhi[(m0 + g + 8) * LDH + c] = (uint32_t)h10 | ((uint32_t)h11 << 16);
        *(uint32_t*)&sAlo[(m0 + g + 8) * LDH + c] = (uint32_t)l10 | ((uint32_t)l11 << 16);
    }
    __syncthreads();
    #pragma unroll
    for (int i = 0; i < 64; i++) {
        int idx = tid + 256 * i;
        int k = idx >> 7;
        int n = idx & 127;
        float w = W2[idx];
        unsigned short h, l;
        split_bf(w, h, l);
        sWhi[n * LDH + k] = h;
        sWlo[n * LDH + k] = l;
    }
    __syncthreads();

    #pragma unroll
    for (int j = 0; j < 16; j++)
        #pragma unroll
        for (int q = 0; q < 4; q++) d[j][q] = 0.f;

    #pragma unroll
    for (int ks = 0; ks < 8; ks++) {
        int k0 = ks * 16;
        uint32_t ah0 = *(uint32_t*)&sAhi[(m0 + g) * LDH + k0 + 2 * t4];
        uint32_t ah1 = *(uint32_t*)&sAhi[(m0 + g + 8) * LDH + k0 + 2 * t4];
        uint32_t ah2 = *(uint32_t*)&sAhi[(m0 + g) * LDH + k0 + 2 * t4 + 8];
        uint32_t ah3 = *(uint32_t*)&sAhi[(m0 + g + 8) * LDH + k0 + 2 * t4 + 8];
        uint32_t al0 = *(uint32_t*)&sAlo[(m0 + g) * LDH + k0 + 2 * t4];
        uint32_t al1 = *(uint32_t*)&sAlo[(m0 + g + 8) * LDH + k0 + 2 * t4];
        uint32_t al2 = *(uint32_t*)&sAlo[(m0 + g) * LDH + k0 + 2 * t4 + 8];
        uint32_t al3 = *(uint32_t*)&sAlo[(m0 + g + 8) * LDH + k0 + 2 * t4 + 8];
        #pragma unroll
        for (int j = 0; j < 16; j++) {
            int nrow = j * 8 + g;
            uint32_t bh0 = *(uint32_t*)&sWhi[nrow * LDH + k0 + 2 * t4];
            uint32_t bh1 = *(uint32_t*)&sWhi[nrow * LDH + k0 + 2 * t4 + 8];
            uint32_t bl0 = *(uint32_t*)&sWlo[nrow * LDH + k0 + 2 * t4];
            uint32_t bl1 = *(uint32_t*)&sWlo[nrow * LDH + k0 + 2 * t4 + 8];
            mma16816(d[j], ah0, ah1, ah2, ah3, bh0, bh1);
            mma16816(d[j], ah0, ah1, ah2, ah3, bl0, bl1);
            mma16816(d[j], al0, al1, al2, al3, bh0, bh1);
        }
    }

    {
        int gr0 = row0 + m0 + g;
        int gr1 = gr0 + 8;
        #pragma unroll
        for (int j = 0; j < 16; j++) {
            int c = j * 8 + 2 * t4;
            float b0v = sB2[c], b1v = sB2[c + 1];
            if (gr0 < NNODES) {
                float2 h0v = *(const float2*)&H0[(size_t)gr0 * HID + c];
                float2 o;
                o.x = d[j][0] + b0v + h0v.x;
                o.y = d[j][1] + b1v + h0v.y;
                o.x = o.x > 0.f ? o.x : 0.f;
                o.y = o.y > 0.f ? o.y : 0.f;
                *(float2*)&OUT[(size_t)gr0 * HID + c] = o;
            }
            if (gr1 < NNODES) {
                float2 h0v = *(const float2*)&H0[(size_t)gr1 * HID + c];
                float2 o;
                o.x = d[j][2] + b0v + h0v.x;
                o.y = d[j][3] + b1v + h0v.y;
                o.x = o.x > 0.f ? o.x : 0.f;
                o.y = o.y > 0.f ? o.y : 0.f;
                *(float2*)&OUT[(size_t)gr1 * HID + c] = o;
            }
        }
    }
}

// ---------------- pooling (batch is sorted) ----------------
__global__ void pool_kernel() {
    const int CH = 256;
    int start = blockIdx.x * CH;
    if (start >= NNODES) return;
    int end = min(start + CH, NNODES);
    int tid = threadIdx.x;
    int gcur = g_bat[start];
    float acc = 0.f;
    for (int n = start; n < end; n++) {
        int b = g_bat[n];
        if (b != gcur) {
            atomicAdd(&g_pooled[gcur * HID + tid], acc);
            acc = 0.f;
            gcur = b;
        }
        acc += g_h[(size_t)n * HID + tid];
    }
    atomicAdd(&g_pooled[gcur * HID + tid], acc);
}

__global__ void final_kernel(const float* __restrict__ fw, const float* __restrict__ fb,
                             float* __restrict__ out) {
    int g = threadIdx.x;
    float s = fb[0];
    #pragma unroll 8
    for (int c = 0; c < HID; c++) s += g_pooled[g * HID + c] * fw[c];
    out[g] = s;
}

// ---------------- launch ----------------
extern "C" void kernel_launch(void* const* d_in, const int* in_sizes, int n_in,
                              void* d_out, int out_size) {
    const float* x       = (const float*)d_in[0];
    const void*  ei      = d_in[1];
    const float* eattr   = (const float*)d_in[2];
    const void*  bat     = d_in[3];
    const float* init_w  = (const float*)d_in[4];
    const float* init_b  = (const float*)d_in[5];
    const float* edge_w  = (const float*)d_in[6];
    const float* edge_b  = (const float*)d_in[7];
    const float* mlp_w1  = (const float*)d_in[8];
    const float* mlp_b1  = (const float*)d_in[9];
    const float* mlp_w2  = (const float*)d_in[10];
    const float* mlp_b2  = (const float*)d_in[11];
    const float* ffn_w   = (const float*)d_in[12];
    const float* ffn_b   = (const float*)d_in[13];
    float* out = (float*)d_out;

    float *p_h = 0, *p_h0 = 0, *p_zin = 0;
    cudaGetSymbolAddress((void**)&p_h,   g_h);
    cudaGetSymbolAddress((void**)&p_h0,  g_h0);
    cudaGetSymbolAddress((void**)&p_zin, g_zin);

    cudaFuncSetAttribute(mlp_fused_kernel, cudaFuncAttributeMaxDynamicSharedMemorySize, SMF_TOTAL);

    const int EBLK = (NEDGES + 255) / 256;
    const int NBLK = (NNODES + 255) / 256;
    const int GBLK = (NNODES + 127) / 128;
    const int PBLK = (2 * NEDGES + 255) / 256;

    detect_kernel<<<1, 256>>>((const int*)ei);
    prologue_kernel<<<PBLK, 256>>>(ei, bat);
    hist_kernel<<<EBLK, 256>>>();
    scan1_kernel<<<SCAN_NB, 1024>>>();
    scan2_kernel<<<1, 64>>>();
    scan3_kernel<<<NBLK, 256>>>();
    scatter_kernel<<<EBLK, 256>>>(eattr);

    init_gemm_kernel<<<GBLK, 256>>>(x, init_w, init_b);

    for (int d = 0; d < DEPTH; d++) {
        edge_gemm_kernel<<<NEDGES / 128, 256>>>(edge_w + (size_t)d * FE * HID,
                                                edge_b + (size_t)d * HID);
        aggr_kernel<<<(NNODES + 7) / 8, 256>>>();
        mlp_fused_kernel<<<GBLK, 256, SMF_TOTAL>>>(
            p_zin, mlp_w1 + (size_t)d * HID * HID, mlp_b1 + (size_t)d * HID,
            mlp_w2 + (size_t)d * HID * HID, mlp_b2 + (size_t)d * HID, p_h0, p_h);
    }

    pool_kernel<<<(NNODES + 255) / 256, 128>>>();
    final_kernel<<<1, 128>>>(ffn_w, ffn_b, out);
}

// round 16
// speedup vs baseline: 2.0535x; 1.0454x over previous
#include <cuda_runtime.h>
#include <cuda_bf16.h>
#include <cstdint>

#define NNODES 50000
#define NEDGES 800000
#define FN 32
#define FE 16
#define HID 128
#define DEPTH 4
#define NGRAPHS 128
#define SCAN_NB 49   // ceil(50000/1024)

// ---------------- scratch (device globals: allocation-free) ----------------
__device__ float g_h[NNODES * HID];
__device__ float g_h0[NNODES * HID];
__device__ float g_zin[NNODES * HID];
__device__ int   g_cnt[NNODES];
__device__ int   g_cnt2[NNODES];
__device__ int   g_rowptr[NNODES + 1];
__device__ int   g_part[SCAN_NB];
__device__ int   g_partoff[SCAN_NB + 1];
__device__ int   g_srcPerm[NEDGES];
__device__ __align__(16) float g_eattr[NEDGES * FE];
__device__ __align__(16) unsigned short g_E[(size_t)NEDGES * HID];    // E buffer 0
__device__ __align__(16) unsigned short g_E2[(size_t)NEDGES * HID];   // E buffer 1
__device__ float g_pooled[NGRAPHS * HID];
__device__ int   g_ei[2 * NEDGES];
__device__ int   g_bat[NNODES];
__device__ int   g_is64;

__device__ __forceinline__ void split_bf(float x, unsigned short& hi, unsigned short& lo) {
    __nv_bfloat16 h = __float2bfloat16(x);
    float r = x - __bfloat162float(h);
    __nv_bfloat16 l = __float2bfloat16(r);
    hi = __bfloat16_as_ushort(h);
    lo = __bfloat16_as_ushort(l);
}

__device__ __forceinline__ void mma16816(float* d, uint32_t a0, uint32_t a1, uint32_t a2, uint32_t a3,
                                         uint32_t b0, uint32_t b1) {
    asm volatile(
        "mma.sync.aligned.m16n8k16.row.col.f32.bf16.bf16.f32 "
        "{%0,%1,%2,%3}, {%4,%5,%6,%7}, {%8,%9}, {%0,%1,%2,%3};"
        : "+f"(d[0]), "+f"(d[1]), "+f"(d[2]), "+f"(d[3])
        : "r"(a0), "r"(a1), "r"(a2), "r"(a3), "r"(b0), "r"(b1));
}

// ---------------- dtype detect (parallel) + merged prologue ----------------
__global__ void detect_kernel(const int* __restrict__ ei_words) {
    __shared__ int nz[8];
    int tid = threadIdx.x;            // 256 threads
    int w = ei_words[2 * tid + 1];
    unsigned int b = __ballot_sync(0xffffffffu, w != 0);
    if ((tid & 31) == 0) nz[tid >> 5] = (b != 0);
    __syncthreads();
    if (tid == 0) {
        int any = 0;
        #pragma unroll
        for (int i = 0; i < 8; i++) any |= nz[i];
        g_is64 = any ? 0 : 1;
    }
}
__global__ void prologue_kernel(const void* __restrict__ ei, const void* __restrict__ bat) {
    int i = blockIdx.x * blockDim.x + threadIdx.x;
    int is64 = g_is64;
    if (i < 2 * NEDGES)
        g_ei[i] = is64 ? (int)((const long long*)ei)[i] : ((const int*)ei)[i];
    if (i < NNODES) {
        g_bat[i] = is64 ? (int)((const long long*)bat)[i] : ((const int*)bat)[i];
        g_cnt[i] = 0;
        g_cnt2[i] = 0;
    }
    if (i < NGRAPHS * HID) g_pooled[i] = 0.f;
}

// ---------------- CSR build ----------------
__global__ void hist_kernel() {
    int e = blockIdx.x * blockDim.x + threadIdx.x;
    if (e < NEDGES) atomicAdd(&g_cnt[g_ei[NEDGES + e]], 1);
}

__global__ __launch_bounds__(1024) void scan1_kernel() {
    __shared__ int warpsum[32];
    int tid = threadIdx.x, lane = tid & 31, wid = tid >> 5;
    int i = blockIdx.x * 1024 + tid;
    int v = (i < NNODES) ? g_cnt[i] : 0;
    int s = v;
    #pragma unroll
    for (int off = 1; off < 32; off <<= 1) {
        int t = __shfl_up_sync(0xffffffffu, s, off);
        if (lane >= off) s += t;
    }
    if (lane == 31) warpsum[wid] = s;
    __syncthreads();
    if (wid == 0) {
        int ws = warpsum[lane];
        #pragma unroll
        for (int off = 1; off < 32; off <<= 1) {
            int t = __shfl_up_sync(0xffffffffu, ws, off);
            if (lane >= off) ws += t;
        }
        warpsum[lane] = ws;
    }
    __syncthreads();
    int woff = (wid > 0) ? warpsum[wid - 1] : 0;
    if (i < NNODES) g_rowptr[i] = s + woff - v;
    if (tid == 1023) g_part[blockIdx.x] = s + woff;
}
__global__ void scan2_kernel() {
    __shared__ int sp[64];
    int tid = threadIdx.x;
    sp[tid] = (tid < SCAN_NB) ? g_part[tid] : 0;
    __syncthreads();
    if (tid == 0) {
        int acc = 0;
        #pragma unroll
        for (int b = 0; b < SCAN_NB; b++) { g_partoff[b] = acc; acc += sp[b]; }
        g_partoff[SCAN_NB] = acc;
    }
}
__global__ void scan3_kernel() {
    int i = blockIdx.x * blockDim.x + threadIdx.x;
    if (i < NNODES) g_rowptr[i] += g_partoff[i >> 10];
    if (i == 0) g_rowptr[NNODES] = g_partoff[SCAN_NB];
}

__global__ void scatter_kernel(const float* __restrict__ ea) {
    int e = blockIdx.x * blockDim.x + threadIdx.x;
    if (e >= NEDGES) return;
    int d = g_ei[NEDGES + e];
    int s = g_ei[e];
    int pos = g_rowptr[d] + atomicAdd(&g_cnt2[d], 1);
    g_srcPerm[pos] = s;
    float4* dst = (float4*)&g_eattr[(size_t)pos * FE];
    const float4* src = (const float4*)&ea[(size_t)e * FE];
    dst[0] = src[0]; dst[1] = src[1]; dst[2] = src[2]; dst[3] = src[3];
}

// ---------------- init GEMM: h = relu(x @ init_w + init_b), h0 = h ----------------
__global__ __launch_bounds__(256) void init_gemm_kernel(const float* __restrict__ X,
                                                        const float* __restrict__ W,
                                                        const float* __restrict__ B) {
    __shared__ float As[128][33];
    __shared__ float Ws[32][128];
    int tid = threadIdx.x;
    int row0 = blockIdx.x * 128;
    int tx = tid & 15, ty = tid >> 4;
    {
        int lr = tid >> 1, lc = (tid & 1) * 16;
        float4 v0, v1, v2, v3;
        if (row0 + lr < NNODES) {
            const float4* p = (const float4*)&X[(size_t)(row0 + lr) * FN + lc];
            v0 = p[0]; v1 = p[1]; v2 = p[2]; v3 = p[3];
        } else { v0 = make_float4(0.f, 0.f, 0.f, 0.f); v1 = v0; v2 = v0; v3 = v0; }
        As[lr][lc + 0] = v0.x; As[lr][lc + 1] = v0.y; As[lr][lc + 2] = v0.z; As[lr][lc + 3] = v0.w;
        As[lr][lc + 4] = v1.x; As[lr][lc + 5] = v1.y; As[lr][lc + 6] = v1.z; As[lr][lc + 7] = v1.w;
        As[lr][lc + 8] = v2.x; As[lr][lc + 9] = v2.y; As[lr][lc + 10] = v2.z; As[lr][lc + 11] = v2.w;
        As[lr][lc + 12] = v3.x; As[lr][lc + 13] = v3.y; As[lr][lc + 14] = v3.z; As[lr][lc + 15] = v3.w;
    }
    {
        int wk = tid >> 3, wc = (tid & 7) * 16;
        const float4* p = (const float4*)&W[(size_t)wk * HID + wc];
        float4 v0 = p[0], v1 = p[1], v2 = p[2], v3 = p[3];
        Ws[wk][wc + 0] = v0.x; Ws[wk][wc + 1] = v0.y; Ws[wk][wc + 2] = v0.z; Ws[wk][wc + 3] = v0.w;
        Ws[wk][wc + 4] = v1.x; Ws[wk][wc + 5] = v1.y; Ws[wk][wc + 6] = v1.z; Ws[wk][wc + 7] = v1.w;
        Ws[wk][wc + 8] = v2.x; Ws[wk][wc + 9] = v2.y; Ws[wk][wc + 10] = v2.z; Ws[wk][wc + 11] = v2.w;
        Ws[wk][wc + 12] = v3.x; Ws[wk][wc + 13] = v3.y; Ws[wk][wc + 14] = v3.z; Ws[wk][wc + 15] = v3.w;
    }
    __syncthreads();
    float acc[8][8];
    #pragma unroll
    for (int i = 0; i < 8; i++)
        #pragma unroll
        for (int j = 0; j < 8; j++) acc[i][j] = 0.f;
    #pragma unroll
    for (int kk = 0; kk < 32; kk++) {
        float a[8];
        #pragma unroll
        for (int i = 0; i < 8; i++) a[i] = As[ty * 8 + i][kk];
        float4 b0 = *(const float4*)&Ws[kk][tx * 8];
        float4 b1 = *(const float4*)&Ws[kk][tx * 8 + 4];
        float b[8] = {b0.x, b0.y, b0.z, b0.w, b1.x, b1.y, b1.z, b1.w};
        #pragma unroll
        for (int i = 0; i < 8; i++)
            #pragma unroll
            for (int j = 0; j < 8; j++) acc[i][j] += a[i] * b[j];
    }
    #pragma unroll
    for (int i = 0; i < 8; i++) {
        int r = row0 + ty * 8 + i;
        if (r < NNODES) {
            #pragma unroll
            for (int j = 0; j < 8; j++) {
                int c = tx * 8 + j;
                float v = acc[i][j] + B[c];
                v = v > 0.f ? v : 0.f;
                g_h[(size_t)r * HID + c] = v;
                g_h0[(size_t)r * HID + c] = v;
            }
        }
    }
}

// ================= edge GEMM: E = g_eattr(perm) @ W_d + b_d, bf16 out (streaming stores) =================
#define EG_LDA 24
__global__ __launch_bounds__(256) void edge_gemm_kernel(const float* __restrict__ Wd,
                                                        const float* __restrict__ Bd,
                                                        unsigned short* __restrict__ E) {
    __shared__ unsigned short sAhi[128 * EG_LDA], sAlo[128 * EG_LDA];
    __shared__ unsigned short sWhi[128 * EG_LDA], sWlo[128 * EG_LDA];
    __shared__ float sB[128];
    int tid = threadIdx.x, wid = tid >> 5, lane = tid & 31;
    int g = lane >> 2, t4 = lane & 3;
    int row0 = blockIdx.x * 128;
    int m0 = wid * 16;

    if (tid < 128) sB[tid] = Bd[tid];
    #pragma unroll
    for (int i = 0; i < 8; i++) {
        int idx = tid + 256 * i;
        int row = idx >> 4, k = idx & 15;
        float v = g_eattr[(size_t)(row0 + row) * FE + k];
        unsigned short h, l;
        split_bf(v, h, l);
        sAhi[row * EG_LDA + k] = h;
        sAlo[row * EG_LDA + k] = l;
    }
    #pragma unroll
    for (int i = 0; i < 8; i++) {
        int idx = tid + 256 * i;
        int k = idx >> 7, n = idx & 127;
        float v = Wd[idx];
        unsigned short h, l;
        split_bf(v, h, l);
        sWhi[n * EG_LDA + k] = h;
        sWlo[n * EG_LDA + k] = l;
    }
    __syncthreads();

    float d[16][4];
    #pragma unroll
    for (int j = 0; j < 16; j++)
        #pragma unroll
        for (int q = 0; q < 4; q++) d[j][q] = 0.f;

    uint32_t ah0 = *(uint32_t*)&sAhi[(m0 + g) * EG_LDA + 2 * t4];
    uint32_t ah1 = *(uint32_t*)&sAhi[(m0 + g + 8) * EG_LDA + 2 * t4];
    uint32_t ah2 = *(uint32_t*)&sAhi[(m0 + g) * EG_LDA + 2 * t4 + 8];
    uint32_t ah3 = *(uint32_t*)&sAhi[(m0 + g + 8) * EG_LDA + 2 * t4 + 8];
    uint32_t al0 = *(uint32_t*)&sAlo[(m0 + g) * EG_LDA + 2 * t4];
    uint32_t al1 = *(uint32_t*)&sAlo[(m0 + g + 8) * EG_LDA + 2 * t4];
    uint32_t al2 = *(uint32_t*)&sAlo[(m0 + g) * EG_LDA + 2 * t4 + 8];
    uint32_t al3 = *(uint32_t*)&sAlo[(m0 + g + 8) * EG_LDA + 2 * t4 + 8];
    #pragma unroll
    for (int j = 0; j < 16; j++) {
        int nrow = j * 8 + g;
        uint32_t bh0 = *(uint32_t*)&sWhi[nrow * EG_LDA + 2 * t4];
        uint32_t bh1 = *(uint32_t*)&sWhi[nrow * EG_LDA + 2 * t4 + 8];
        uint32_t bl0 = *(uint32_t*)&sWlo[nrow * EG_LDA + 2 * t4];
        uint32_t bl1 = *(uint32_t*)&sWlo[nrow * EG_LDA + 2 * t4 + 8];
        mma16816(d[j], ah0, ah1, ah2, ah3, bh0, bh1);
        mma16816(d[j], ah0, ah1, ah2, ah3, bl0, bl1);
        mma16816(d[j], al0, al1, al2, al3, bh0, bh1);
    }

    size_t e0 = (size_t)(row0 + m0 + g) * HID;
    size_t e1 = (size_t)(row0 + m0 + g + 8) * HID;
    #pragma unroll
    for (int j = 0; j < 16; j++) {
        int c = j * 8 + 2 * t4;
        float b0v = sB[c], b1v = sB[c + 1];
        unsigned short u00 = __bfloat16_as_ushort(__float2bfloat16(d[j][0] + b0v));
        unsigned short u01 = __bfloat16_as_ushort(__float2bfloat16(d[j][1] + b1v));
        unsigned short u10 = __bfloat16_as_ushort(__float2bfloat16(d[j][2] + b0v));
        unsigned short u11 = __bfloat16_as_ushort(__float2bfloat16(d[j][3] + b1v));
        __stcs((unsigned int*)&E[e0 + c], (unsigned int)u00 | ((unsigned int)u01 << 16));
        __stcs((unsigned int*)&E[e1 + c], (unsigned int)u10 | ((unsigned int)u11 << 16));
    }
}

// ---------------- aggregation: warp per node, 4-way unroll, streaming E reads ----------------
__device__ __forceinline__ void aggr_step(float4& acc, const unsigned short* __restrict__ E,
                                          int s, int e, int c4) {
    float4 hv = *(const float4*)&g_h[(size_t)s * HID + c4];
    uint2 ev = __ldcs((const uint2*)&E[(size_t)e * HID + c4]);
    float e0 = __bfloat162float(__ushort_as_bfloat16((unsigned short)(ev.x & 0xFFFF)));
    float e1 = __bfloat162float(__ushort_as_bfloat16((unsigned short)(ev.x >> 16)));
    float e2 = __bfloat162float(__ushort_as_bfloat16((unsigned short)(ev.y & 0xFFFF)));
    float e3 = __bfloat162float(__ushort_as_bfloat16((unsigned short)(ev.y >> 16)));
    acc.x += fmaxf(hv.x + e0, 0.f);
    acc.y += fmaxf(hv.y + e1, 0.f);
    acc.z += fmaxf(hv.z + e2, 0.f);
    acc.w += fmaxf(hv.w + e3, 0.f);
}

__global__ __launch_bounds__(256) void aggr_kernel(const unsigned short* __restrict__ E) {
    int wid = threadIdx.x >> 5, lane = threadIdx.x & 31;
    int n = blockIdx.x * 8 + wid;
    if (n >= NNODES) return;
    int c4 = lane * 4;
    int r0 = g_rowptr[n], r1 = g_rowptr[n + 1];
    float4 acc = *(const float4*)&g_h[(size_t)n * HID + c4];
    int e = r0;
    for (; e + 4 <= r1; e += 4) {
        int s0 = g_srcPerm[e];
        int s1 = g_srcPerm[e + 1];
        int s2 = g_srcPerm[e + 2];
        int s3 = g_srcPerm[e + 3];
        float4 h0 = *(const float4*)&g_h[(size_t)s0 * HID + c4];
        float4 h1 = *(const float4*)&g_h[(size_t)s1 * HID + c4];
        float4 h2 = *(const float4*)&g_h[(size_t)s2 * HID + c4];
        float4 h3 = *(const float4*)&g_h[(size_t)s3 * HID + c4];
        uint2 v0 = __ldcs((const uint2*)&E[(size_t)e * HID + c4]);
        uint2 v1 = __ldcs((const uint2*)&E[(size_t)(e + 1) * HID + c4]);
        uint2 v2 = __ldcs((const uint2*)&E[(size_t)(e + 2) * HID + c4]);
        uint2 v3 = __ldcs((const uint2*)&E[(size_t)(e + 3) * HID + c4]);
        #pragma unroll
        for (int q = 0; q < 4; q++) {
            float4 hv = (q == 0) ? h0 : (q == 1) ? h1 : (q == 2) ? h2 : h3;
            uint2 ev = (q == 0) ? v0 : (q == 1) ? v1 : (q == 2) ? v2 : v3;
            float e0 = __bfloat162float(__ushort_as_bfloat16((unsigned short)(ev.x & 0xFFFF)));
            float e1 = __bfloat162float(__ushort_as_bfloat16((unsigned short)(ev.x >> 16)));
            float e2 = __bfloat162float(__ushort_as_bfloat16((unsigned short)(ev.y & 0xFFFF)));
            float e3 = __bfloat162float(__ushort_as_bfloat16((unsigned short)(ev.y >> 16)));
            acc.x += fmaxf(hv.x + e0, 0.f);
            acc.y += fmaxf(hv.y + e1, 0.f);
            acc.z += fmaxf(hv.z + e2, 0.f);
            acc.w += fmaxf(hv.w + e3, 0.f);
        }
    }
    for (; e < r1; e++) aggr_step(acc, E, g_srcPerm[e], e, c4);
    *(float4*)&g_zin[(size_t)n * HID + c4] = acc;
}

// ================= fused node-MLP via mma.sync (bf16 split hi/lo) =================
#define LDH 136
#define SMF_B1 0
#define SMF_B2 512
#define SMF_AHI 1024
#define SMF_ALO (SMF_AHI + 128 * LDH * 2)
#define SMF_WHI (SMF_ALO + 128 * LDH * 2)
#define SMF_WLO (SMF_WHI + 128 * LDH * 2)
#define SMF_TOTAL (SMF_WLO + 128 * LDH * 2)

__global__ __launch_bounds__(256) void mlp_fused_kernel(
    const float* __restrict__ A, const float* __restrict__ W1, const float* __restrict__ B1,
    const float* __restrict__ W2, const float* __restrict__ B2,
    const float* __restrict__ H0, float* __restrict__ OUT)
{
    extern __shared__ __align__(16) char smem[];
    unsigned short* sAhi = (unsigned short*)(smem + SMF_AHI);
    unsigned short* sAlo = (unsigned short*)(smem + SMF_ALO);
    unsigned short* sWhi = (unsigned short*)(smem + SMF_WHI);
    unsigned short* sWlo = (unsigned short*)(smem + SMF_WLO);
    float* sB1 = (float*)(smem + SMF_B1);
    float* sB2 = (float*)(smem + SMF_B2);

    int tid = threadIdx.x, wid = tid >> 5, lane = tid & 31;
    int g = lane >> 2, t4 = lane & 3;
    int row0 = blockIdx.x * 128;
    int m0 = wid * 16;

    if (tid < 128) { sB1[tid] = B1[tid]; sB2[tid] = B2[tid]; }

    #pragma unroll
    for (int i = 0; i < 32; i++) {
        int idx2 = tid + 256 * i;
        int row = idx2 >> 6;
        int col = (idx2 & 63) * 2;
        int gr = row0 + row;
        float2 v = (gr < NNODES) ? *(const float2*)&A[(size_t)gr * HID + col]
                                 : make_float2(0.f, 0.f);
        unsigned short hx, lx, hy, ly;
        split_bf(v.x, hx, lx); split_bf(v.y, hy, ly);
        *(uint32_t*)&sAhi[row * LDH + col] = (uint32_t)hx | ((uint32_t)hy << 16);
        *(uint32_t*)&sAlo[row * LDH + col] = (uint32_t)lx | ((uint32_t)ly << 16);
    }
    #pragma unroll
    for (int i = 0; i < 64; i++) {
        int idx = tid + 256 * i;
        int k = idx >> 7;
        int n = idx & 127;
        float w = W1[idx];
        unsigned short h, l;
        split_bf(w, h, l);
        sWhi[n * LDH + k] = h;
        sWlo[n * LDH + k] = l;
    }
    __syncthreads();

    float d[16][4];
    #pragma unroll
    for (int j = 0; j < 16; j++)
        #pragma unroll
        for (int q = 0; q < 4; q++) d[j][q] = 0.f;

    #pragma unroll
    for (int ks = 0; ks < 8; ks++) {
        int k0 = ks * 16;
        uint32_t ah0 = *(uint32_t*)&sAhi[(m0 + g) * LDH + k0 + 2 * t4];
        uint32_t ah1 = *(uint32_t*)&sAhi[(m0 + g + 8) * LDH + k0 + 2 * t4];
        uint32_t ah2 = *(uint32_t*)&sAhi[(m0 + g) * LDH + k0 + 2 * t4 + 8];
        uint32_t ah3 = *(uint32_t*)&sAhi[(m0 + g + 8) * LDH + k0 + 2 * t4 + 8];
        uint32_t al0 = *(uint32_t*)&sAlo[(m0 + g) * LDH + k0 + 2 * t4];
        uint32_t al1 = *(uint32_t*)&sAlo[(m0 + g + 8) * LDH + k0 + 2 * t4];
        uint32_t al2 = *(uint32_t*)&sAlo[(m0 + g) * LDH + k0 + 2 * t4 + 8];
        uint32_t al3 = *(uint32_t*)&sAlo[(m0 + g + 8) * LDH + k0 + 2 * t4 + 8];
        #pragma unroll
        for (int j = 0; j < 16; j++) {
            int nrow = j * 8 + g;
            uint32_t bh0 = *(uint32_t*)&sWhi[nrow * LDH + k0 + 2 * t4];
            uint32_t bh1 = *(uint32_t*)&sWhi[nrow * LDH + k0 + 2 * t4 + 8];
            uint32_t bl0 = *(uint32_t*)&sWlo[nrow * LDH + k0 + 2 * t4];
            uint32_t bl1 = *(uint32_t*)&sWlo[nrow * LDH + k0 + 2 * t4 + 8];
            mma16816(d[j], ah0, ah1, ah2, ah3, bh0, bh1);
            mma16816(d[j], ah0, ah1, ah2, ah3, bl0, bl1);
            mma16816(d[j], al0, al1, al2, al3, bh0, bh1);
        }
    }

    #pragma unroll
    for (int j = 0; j < 16; j++) {
        int c = j * 8 + 2 * t4;
        float b0v = sB1[c], b1v = sB1[c + 1];
        float v00 = d[j][0] + b0v, v01 = d[j][1] + b1v;
        float v10 = d[j][2] + b0v, v11 = d[j][3] + b1v;
        v00 = v00 > 0.f ? v00 : 0.f; v01 = v01 > 0.f ? v01 : 0.f;
        v10 = v10 > 0.f ? v10 : 0.f; v11 = v11 > 0.f ? v11 : 0.f;
        unsigned short h00, l00, h01, l01, h10, l10, h11, l11;
        split_bf(v00, h00, l00); split_bf(v01, h01, l01);
        split_bf(v10, h10, l10); split_bf(v11, h11, l11);
        *(uint32_t*)&sAhi[(m0 + g) * LDH + c]     = (uint32_t)h00 | ((uint32_t)h01 << 16);
        *(uint32_t*)&sAlo[(m0 + g) * LDH + c]     = (uint32_t)l00 | ((uint32_t)l01 << 16);
        *(uint32_t*)&sAhi[(m0 + g + 8) * LDH + c] = (uint32_t)h10 | ((uint32_t)h11 << 16);
        *(uint32_t*)&sAlo[(m0 + g + 8) * LDH + c] = (uint32_t)l10 | ((uint32_t)l11 << 16);
    }
    __syncthreads();
    #pragma unroll
    for (int i = 0; i < 64; i++) {
        int idx = tid + 256 * i;
        int k = idx >> 7;
        int n = idx & 127;
        float w = W2[idx];
        unsigned short h, l;
        split_bf(w, h, l);
        sWhi[n * LDH + k] = h;
        sWlo[n * LDH + k] = l;
    }
    __syncthreads();

    #pragma unroll
    for (int j = 0; j < 16; j++)
        #pragma unroll
        for (int q = 0; q < 4; q++) d[j][q] = 0.f;

    #pragma unroll
    for (int ks = 0; ks < 8; ks++) {
        int k0 = ks * 16;
        uint32_t ah0 = *(uint32_t*)&sAhi[(m0 + g) * LDH + k0 + 2 * t4];
        uint32_t ah1 = *(uint32_t*)&sAhi[(m0 + g + 8) * LDH + k0 + 2 * t4];
        uint32_t ah2 = *(uint32_t*)&sAhi[(m0 + g) * LDH + k0 + 2 * t4 + 8];
        uint32_t ah3 = *(uint32_t*)&sAhi[(m0 + g + 8) * LDH + k0 + 2 * t4 + 8];
        uint32_t al0 = *(uint32_t*)&sAlo[(m0 + g) * LDH + k0 + 2 * t4];
        uint32_t al1 = *(uint32_t*)&sAlo[(m0 + g + 8) * LDH + k0 + 2 * t4];
        uint32_t al2 = *(uint32_t*)&sAlo[(m0 + g) * LDH + k0 + 2 * t4 + 8];
        uint32_t al3 = *(uint32_t*)&sAlo[(m0 + g + 8) * LDH + k0 + 2 * t4 + 8];
        #pragma unroll
        for (int j = 0; j < 16; j++) {
            int nrow = j * 8 + g;
            uint32_t bh0 = *(uint32_t*)&sWhi[nrow * LDH + k0 + 2 * t4];
            uint32_t bh1 = *(uint32_t*)&sWhi[nrow * LDH + k0 + 2 * t4 + 8];
            uint32_t bl0 = *(uint32_t*)&sWlo[nrow * LDH + k0 + 2 * t4];
            uint32_t bl1 = *(uint32_t*)&sWlo[nrow * LDH + k0 + 2 * t4 + 8];
            mma16816(d[j], ah0, ah1, ah2, ah3, bh0, bh1);
            mma16816(d[j], ah0, ah1, ah2, ah3, bl0, bl1);
            mma16816(d[j], al0, al1, al2, al3, bh0, bh1);
        }
    }

    {
        int gr0 = row0 + m0 + g;
        int gr1 = gr0 + 8;
        #pragma unroll
        for (int j = 0; j < 16; j++) {
            int c = j * 8 + 2 * t4;
            float b0v = sB2[c], b1v = sB2[c + 1];
            if (gr0 < NNODES) {
                float2 h0v = *(const float2*)&H0[(size_t)gr0 * HID + c];
                float2 o;
                o.x = d[j][0] + b0v + h0v.x;
                o.y = d[j][1] + b1v + h0v.y;
                o.x = o.x > 0.f ? o.x : 0.f;
                o.y = o.y > 0.f ? o.y : 0.f;
                *(float2*)&OUT[(size_t)gr0 * HID + c] = o;
            }
            if (gr1 < NNODES) {
                float2 h0v = *(const float2*)&H0[(size_t)gr1 * HID + c];
                float2 o;
                o.x = d[j][2] + b0v + h0v.x;
                o.y = d[j][3] + b1v + h0v.y;
                o.x = o.x > 0.f ? o.x : 0.f;
                o.y = o.y > 0.f ? o.y : 0.f;
                *(float2*)&OUT[(size_t)gr1 * HID + c] = o;
            }
        }
    }
}

// ---------------- pooling (batch is sorted) ----------------
__global__ void pool_kernel() {
    const int CH = 256;
    int start = blockIdx.x * CH;
    if (start >= NNODES) return;
    int end = min(start + CH, NNODES);
    int tid = threadIdx.x;
    int gcur = g_bat[start];
    float acc = 0.f;
    for (int n = start; n < end; n++) {
        int b = g_bat[n];
        if (b != gcur) {
            atomicAdd(&g_pooled[gcur * HID + tid], acc);
            acc = 0.f;
            gcur = b;
        }
        acc += g_h[(size_t)n * HID + tid];
    }
    atomicAdd(&g_pooled[gcur * HID + tid], acc);
}

__global__ void final_kernel(const float* __restrict__ fw, const float* __restrict__ fb,
                             float* __restrict__ out) {
    int g = threadIdx.x;
    float s = fb[0];
    #pragma unroll 8
    for (int c = 0; c < HID; c++) s += g_pooled[g * HID + c] * fw[c];
    out[g] = s;
}

// ---------------- launch ----------------
extern "C" void kernel_launch(void* const* d_in, const int* in_sizes, int n_in,
                              void* d_out, int out_size) {
    const float* x       = (const float*)d_in[0];
    const void*  ei      = d_in[1];
    const float* eattr   = (const float*)d_in[2];
    const void*  bat     = d_in[3];
    const float* init_w  = (const float*)d_in[4];
    const float* init_b  = (const float*)d_in[5];
    const float* edge_w  = (const float*)d_in[6];
    const float* edge_b  = (const float*)d_in[7];
    const float* mlp_w1  = (const float*)d_in[8];
    const float* mlp_b1  = (const float*)d_in[9];
    const float* mlp_w2  = (const float*)d_in[10];
    const float* mlp_b2  = (const float*)d_in[11];
    const float* ffn_w   = (const float*)d_in[12];
    const float* ffn_b   = (const float*)d_in[13];
    float* out = (float*)d_out;

    float *p_h = 0, *p_h0 = 0, *p_zin = 0;
    unsigned short *p_E[2] = {0, 0};
    cudaGetSymbolAddress((void**)&p_h,    g_h);
    cudaGetSymbolAddress((void**)&p_h0,   g_h0);
    cudaGetSymbolAddress((void**)&p_zin,  g_zin);
    cudaGetSymbolAddress((void**)&p_E[0], g_E);
    cudaGetSymbolAddress((void**)&p_E[1], g_E2);

    cudaFuncSetAttribute(mlp_fused_kernel, cudaFuncAttributeMaxDynamicSharedMemorySize, SMF_TOTAL);

    // side stream + events for edge-GEMM overlap (host objects; created per call,
    // intentionally not destroyed — replays re-execute the captured graph, not this function)
    cudaStream_t s2;
    cudaStreamCreate(&s2);
    cudaEvent_t evScatter, evE[DEPTH], evAG[DEPTH];
    cudaEventCreateWithFlags(&evScatter, cudaEventDisableTiming);
    for (int d = 0; d < DEPTH; d++) {
        cudaEventCreateWithFlags(&evE[d], cudaEventDisableTiming);
        cudaEventCreateWithFlags(&evAG[d], cudaEventDisableTiming);
    }

    const int EBLK = (NEDGES + 255) / 256;
    const int NBLK = (NNODES + 255) / 256;
    const int GBLK = (NNODES + 127) / 128;
    const int PBLK = (2 * NEDGES + 255) / 256;

    detect_kernel<<<1, 256>>>((const int*)ei);
    prologue_kernel<<<PBLK, 256>>>(ei, bat);
    hist_kernel<<<EBLK, 256>>>();
    scan1_kernel<<<SCAN_NB, 1024>>>();
    scan2_kernel<<<1, 64>>>();
    scan3_kernel<<<NBLK, 256>>>();
    scatter_kernel<<<EBLK, 256>>>(eattr);
    cudaEventRecord(evScatter, 0);
    cudaStreamWaitEvent(s2, evScatter, 0);

    init_gemm_kernel<<<GBLK, 256>>>(x, init_w, init_b);

    for (int d = 0; d < DEPTH; d++) {
        // edge GEMM on side stream (double-buffered E)
        if (d >= 2) cudaStreamWaitEvent(s2, evAG[d - 2], 0);
        edge_gemm_kernel<<<NEDGES / 128, 256, 0, s2>>>(edge_w + (size_t)d * FE * HID,
                                                       edge_b + (size_t)d * HID, p_E[d & 1]);
        cudaEventRecord(evE[d], s2);

        // main stream consumes E
        cudaStreamWaitEvent(0, evE[d], 0);
        aggr_kernel<<<(NNODES + 7) / 8, 256>>>(p_E[d & 1]);
        cudaEventRecord(evAG[d], 0);
        mlp_fused_kernel<<<GBLK, 256, SMF_TOTAL>>>(
            p_zin, mlp_w1 + (size_t)d * HID * HID, mlp_b1 + (size_t)d * HID,
            mlp_w2 + (size_t)d * HID * HID, mlp_b2 + (size_t)d * HID, p_h0, p_h);
    }

    pool_kernel<<<(NNODES + 255) / 256, 128>>>();
    final_kernel<<<1, 128>>>(ffn_w, ffn_b, out);
}